// round 7
// baseline (speedup 1.0000x reference)
#include <cuda_runtime.h>
#include <math.h>

// ---------------- model constants ----------------
#define D_    1024
#define V_    32000
#define DFF_  4096
#define H_    16
#define T_    2048
#define HD_   64
#define CAP_  512
#define NHOPS_ 4

// ---------------- workspace ----------------
constexpr size_t SZ_TD   = (size_t)T_ * D_;
constexpr size_t OFF_H   = 0;
constexpr size_t OFF_XN  = OFF_H   + SZ_TD;
constexpr size_t OFF_Q   = OFF_XN  + SZ_TD;
constexpr size_t OFF_K   = OFF_Q   + SZ_TD;
constexpr size_t OFF_V   = OFF_K   + SZ_TD;
constexpr size_t OFF_AO  = OFF_V   + SZ_TD;
constexpr size_t OFF_FFN = OFF_AO  + SZ_TD;
constexpr size_t OFF_SC  = OFF_FFN + (size_t)T_ * DFF_;
constexpr size_t OFF_XIN = OFF_SC  + (size_t)H_ * T_ * T_;
constexpr size_t OFF_EOUT= OFF_XIN + (size_t)8 * CAP_ * D_;
constexpr size_t OFF_COS = OFF_EOUT+ (size_t)8 * CAP_ * D_;
constexpr size_t OFF_SIN = OFF_COS + (size_t)T_ * HD_;
constexpr size_t OFF_COSR= OFF_SIN + (size_t)T_ * HD_;
constexpr size_t OFF_SINR= OFF_COSR+ (size_t)8 * CAP_ * HD_;
constexpr size_t OFF_LG  = OFF_SINR+ (size_t)8 * CAP_ * HD_;
constexpr size_t OFF_RHO = OFF_LG  + (size_t)T_ * 9;
constexpr size_t WS_TOTAL= OFF_RHO + (size_t)T_;
__device__ float g_ws[WS_TOTAL];

// double-precision prefix sums of cos/sin: (T+1) x HD each
constexpr size_t OFF_PC = 0;
constexpr size_t OFF_PS = (size_t)(T_ + 1) * HD_;
constexpr size_t WSD_TOTAL = 2 * (size_t)(T_ + 1) * HD_;
__device__ double g_wsd[WSD_TOTAL];

constexpr size_t IOFF_SEL   = 0;                      // T*2
constexpr size_t IOFF_STOK  = IOFF_SEL  + 2 * T_;     // 9*CAP
constexpr size_t IOFF_TSLOT = IOFF_STOK + 9 * CAP_;   // T*2
constexpr size_t IOFF_ECNT  = IOFF_TSLOT + 2 * T_;    // 9
constexpr size_t IOFF_EOV   = IOFF_ECNT + 9;          // 9
constexpr size_t WSI_TOTAL  = IOFF_EOV + 9;
__device__ int g_wsi[WSI_TOTAL];

// ---------------- generic strided-batched SGEMM ----------------
// C = alpha * A(MxK) * B    (TB ? B is NxK row-major, C=A*B^T : B is KxN row-major)
// ACC: C += result
template<bool TB, bool ACC>
__global__ void sgemm_k(const float* __restrict__ A, const float* __restrict__ B,
                        float* __restrict__ C,
                        int M, int N, int K, int lda, int ldb, int ldc,
                        long long sA, long long sB, long long sC, float alpha)
{
    __shared__ float As[16][128];
    __shared__ float Bs[16][128];
    int b = blockIdx.z;
    A += (size_t)b * sA; B += (size_t)b * sB; C += (size_t)b * sC;
    int m0 = blockIdx.y * 128, n0 = blockIdx.x * 128;
    int tid = threadIdx.x;
    int tx = tid & 15, ty = tid >> 4;
    float acc[8][8];
    #pragma unroll
    for (int i = 0; i < 8; i++)
        #pragma unroll
        for (int j = 0; j < 8; j++) acc[i][j] = 0.f;

    for (int k0 = 0; k0 < K; k0 += 16) {
        #pragma unroll
        for (int i = 0; i < 8; i++) {
            int idx = tid + i * 256;
            int k = idx & 15, m = idx >> 4;
            int gm = m0 + m, gk = k0 + k;
            As[k][m] = (gm < M && gk < K) ? A[(long long)gm * lda + gk] : 0.f;
        }
        #pragma unroll
        for (int i = 0; i < 8; i++) {
            int idx = tid + i * 256;
            if (!TB) {
                int n = idx & 127, k = idx >> 7;
                int gk = k0 + k, gn = n0 + n;
                Bs[k][n] = (gk < K && gn < N) ? B[(long long)gk * ldb + gn] : 0.f;
            } else {
                int k = idx & 15, n = idx >> 4;
                int gn = n0 + n, gk = k0 + k;
                Bs[k][n] = (gn < N && gk < K) ? B[(long long)gn * ldb + gk] : 0.f;
            }
        }
        __syncthreads();
        #pragma unroll
        for (int k = 0; k < 16; k++) {
            float ra[8], rb[8];
            #pragma unroll
            for (int i = 0; i < 8; i++) ra[i] = As[k][ty * 8 + i];
            #pragma unroll
            for (int i = 0; i < 8; i++) rb[i] = Bs[k][tx * 8 + i];
            #pragma unroll
            for (int i = 0; i < 8; i++)
                #pragma unroll
                for (int j = 0; j < 8; j++)
                    acc[i][j] += ra[i] * rb[j];
        }
        __syncthreads();
    }
    #pragma unroll
    for (int i = 0; i < 8; i++) {
        int gm = m0 + ty * 8 + i;
        if (gm >= M) continue;
        #pragma unroll
        for (int j = 0; j < 8; j++) {
            int gn = n0 + tx * 8 + j;
            if (gn >= N) continue;
            long long off = (long long)gm * ldc + gn;
            float v = alpha * acc[i][j];
            if (ACC) C[off] += v; else C[off] = v;
        }
    }
}

// ---------------- small kernels ----------------
__global__ void rope_tab_k(float* __restrict__ cs, float* __restrict__ sn)
{
    int t = blockIdx.x, i = threadIdx.x;           // i in [0,64)
    int j = i & 31;
    float ex = (float)(2 * j) / 64.0f;
    float inv = (float)(1.0 / pow(10000.0, (double)ex));
    float ang = (float)t * inv;
    cs[t * HD_ + i] = cosf(ang);
    sn[t * HD_ + i] = sinf(ang);
}

// prefix sums of cos/sin over tokens, double precision. <<<1, 64>>>
__global__ void prefix_k(const float* __restrict__ cs, const float* __restrict__ sn,
                         double* __restrict__ pc, double* __restrict__ ps)
{
    int d = threadIdx.x;
    double a = 0.0, b = 0.0;
    pc[d] = 0.0; ps[d] = 0.0;
    for (int t = 0; t < T_; t++) {
        a += (double)cs[t * HD_ + d];
        b += (double)sn[t * HD_ + d];
        pc[(t + 1) * HD_ + d] = a;
        ps[(t + 1) * HD_ + d] = b;
    }
}

__global__ void embed_k(const int* __restrict__ ids, const float* __restrict__ em,
                        float* __restrict__ h)
{
    int t = blockIdx.x;
    long long r = ids[t];
    const float* src = em + r * D_;
    float* dst = h + (size_t)t * D_;
    for (int d = threadIdx.x; d < D_; d += 256) dst[d] = src[d];
}

__global__ void rmsnorm_k(const float* __restrict__ x, const float* __restrict__ ln,
                          float* __restrict__ y)
{
    int row = blockIdx.x;
    const float* xr = x + (size_t)row * D_;
    float* yr = y + (size_t)row * D_;
    __shared__ float red[256];
    float s = 0.f;
    for (int d = threadIdx.x; d < D_; d += 256) { float v = xr[d]; s += v * v; }
    red[threadIdx.x] = s; __syncthreads();
    for (int st = 128; st > 0; st >>= 1) {
        if (threadIdx.x < st) red[threadIdx.x] += red[threadIdx.x + st];
        __syncthreads();
    }
    float r = rsqrtf(red[0] / (float)D_ + 1e-6f);
    for (int d = threadIdx.x; d < D_; d += 256) yr[d] = xr[d] * r * ln[d];
}

__global__ void rope_k(float* __restrict__ q, float* __restrict__ k,
                       const float* __restrict__ cs, const float* __restrict__ sn)
{
    int row = blockIdx.x;
    int tid = threadIdx.x;                 // 512 = 16 heads * 32
    int h = tid >> 5, i = tid & 31;
    float c1 = cs[row * HD_ + i],      s1 = sn[row * HD_ + i];
    float c2 = cs[row * HD_ + i + 32], s2 = sn[row * HD_ + i + 32];
    long long base = (long long)row * D_ + h * HD_ + i;
    float q0 = q[base], q1 = q[base + 32];
    q[base]      = q0 * c1 - q1 * s1;
    q[base + 32] = q1 * c2 + q0 * s2;
    float k0 = k[base], k1 = k[base + 32];
    k[base]      = k0 * c1 - k1 * s1;
    k[base + 32] = k1 * c2 + k0 * s2;
}

__global__ void softmax_causal_k(float* __restrict__ sc, int S)
{
    int i = blockIdx.x, h = blockIdx.y;
    float* row = sc + ((size_t)h * S + i) * (size_t)S;
    int valid = i + 1;
    __shared__ float red[256];
    int tid = threadIdx.x;
    float m = -1e30f;
    for (int j = tid; j < valid; j += 256) m = fmaxf(m, row[j]);
    red[tid] = m; __syncthreads();
    for (int st = 128; st > 0; st >>= 1) {
        if (tid < st) red[tid] = fmaxf(red[tid], red[tid + st]);
        __syncthreads();
    }
    m = red[0]; __syncthreads();
    float sum = 0.f;
    for (int j = tid; j < valid; j += 256) { float e = expf(row[j] - m); row[j] = e; sum += e; }
    red[tid] = sum; __syncthreads();
    for (int st = 128; st > 0; st >>= 1) {
        if (tid < st) red[tid] += red[tid + st];
        __syncthreads();
    }
    float inv = 1.0f / red[0];
    for (int j = tid; j < valid; j += 256) row[j] *= inv;
    for (int j = valid + tid; j < S; j += 256) row[j] = 0.f;
}

__global__ void gelu_k(float* __restrict__ x, long long n)
{
    for (long long i = blockIdx.x * (long long)blockDim.x + threadIdx.x; i < n;
         i += (long long)gridDim.x * blockDim.x) {
        float v = x[i];
        float t = tanhf(0.7978845608028654f * (v + 0.044715f * v * v * v));
        x[i] = 0.5f * v * (1.f + t);
    }
}

__global__ void top2_k(const float* __restrict__ lg, int* __restrict__ sel,
                       float* __restrict__ rho)
{
    int t = blockIdx.x * blockDim.x + threadIdx.x;
    if (t >= T_) return;
    const float* l = lg + (size_t)t * 9;
    int e0 = 0; float b0 = l[0];
    for (int e = 1; e < 9; e++) if (l[e] > b0) { b0 = l[e]; e0 = e; }
    int e1 = -1; float b1 = -1e30f;
    for (int e = 0; e < 9; e++) { if (e == e0) continue; if (l[e] > b1) { b1 = l[e]; e1 = e; } }
    sel[2 * t] = e0; sel[2 * t + 1] = e1;
    rho[t] = 0.5f * (float)((e0 < 8 ? 1 : 0) + (e1 < 8 ? 1 : 0));
}

__global__ void clear_k(int* __restrict__ p, int n)
{
    int i = blockIdx.x * blockDim.x + threadIdx.x;
    if (i < n) p[i] = -1;
}

// per-expert sequential scan: slot tokens, token->slot map, total count, first
// overflow token (the token with rank == CAP, i.e. (CAP+1)-th selected).
__global__ void scan_k(const int* __restrict__ sel, int* __restrict__ stok,
                       int* __restrict__ tslot, int* __restrict__ ecnt,
                       int* __restrict__ eov)
{
    int e = threadIdx.x;
    if (e >= 9) return;
    int cnt = 0, ov = T_;
    for (int t = 0; t < T_; t++) {
        #pragma unroll
        for (int j = 0; j < 2; j++) {
            if (sel[2 * t + j] == e) {
                int r = cnt++;
                if (r < CAP_) { stok[e * CAP_ + r] = t; tslot[2 * t + j] = r; }
                else          { tslot[2 * t + j] = -1; if (r == CAP_) ov = t; }
            }
        }
    }
    ecnt[e] = cnt;
    eov[e] = ov;
}

__global__ void gather_k(const float* __restrict__ h, const int* __restrict__ stok,
                         float* __restrict__ xin)
{
    int row = blockIdx.x;                 // 0..8*CAP-1, experts 0..7
    int tok = stok[row];
    float* xo = xin + (size_t)row * D_;
    if (tok >= 0) {
        const float* hr = h + (size_t)tok * D_;
        for (int d = threadIdx.x; d < D_; d += 256) xo[d] = 0.5f * hr[d];
    } else {
        for (int d = threadIdx.x; d < D_; d += 256) xo[d] = 0.f;
    }
}

// cos_r/sin_r per the reference's raw-slot einsum: slot is NOT a permutation.
// Every token contributes to the slot equal to clip(rank, 0, CAP-1) as long as
// rank < CAP, where rank[t] = (#selected tokens <= t) - 1. So slot c sums
// cos/sin over a token interval [start, end):
//   c == 0           : start = 0 (covers rank == -1 region too)
//   c  > 0           : start = stok[c]
//   end = stok[c+1] if c+1 < min(m, CAP); eov if c+1 == CAP < m; else T.
// Empty expert (m == 0): slot 0 sums ALL tokens.
__global__ void fill_cossin_k(const int* __restrict__ stok, const int* __restrict__ ecnt,
                              const int* __restrict__ eov,
                              const double* __restrict__ pc, const double* __restrict__ ps,
                              float* __restrict__ csr, float* __restrict__ snr)
{
    int row = blockIdx.x;               // 8*CAP
    int e = row / CAP_, c = row % CAP_;
    int d = threadIdx.x;                // 64
    int m = ecnt[e];
    int mc = m < CAP_ ? m : CAP_;
    bool active = (c < mc) || (m == 0 && c == 0);
    if (!active) {
        csr[row * HD_ + d] = 0.f;
        snr[row * HD_ + d] = 0.f;
        return;
    }
    int start = (c == 0) ? 0 : stok[e * CAP_ + c];
    int end;
    if (m == 0)            end = T_;
    else if (c + 1 < m)    end = (c + 1 < CAP_) ? stok[e * CAP_ + c + 1] : eov[e];
    else                   end = T_;
    csr[row * HD_ + d] = (float)(pc[end * HD_ + d] - pc[start * HD_ + d]);
    snr[row * HD_ + d] = (float)(ps[end * HD_ + d] - ps[start * HD_ + d]);
}

__global__ void scale_k(float* __restrict__ h, const float* __restrict__ rho)
{
    int t = blockIdx.x;
    float f = 1.0f - rho[t];
    float* hr = h + (size_t)t * D_;
    for (int d = threadIdx.x; d < D_; d += 256) hr[d] *= f;
}

__global__ void combine_k(float* __restrict__ h, const float* __restrict__ eout,
                          const int* __restrict__ sel, const int* __restrict__ tslot)
{
    int t = blockIdx.x;
    float* hr = h + (size_t)t * D_;
    #pragma unroll
    for (int j = 0; j < 2; j++) {
        int e = sel[2 * t + j];
        int s = tslot[2 * t + j];
        if (e < 8 && s >= 0) {
            const float* src = eout + ((size_t)e * CAP_ + s) * D_;
            for (int d = threadIdx.x; d < D_; d += 256) hr[d] += 0.5f * src[d];
        }
    }
}

// ---------------- host helpers ----------------
static void gemm(bool tb, bool acc, const float* A, const float* B, float* C,
                 int M, int N, int K, int lda, int ldb, int ldc,
                 long long sA, long long sB, long long sC, int batch, float alpha)
{
    dim3 g((N + 127) / 128, (M + 127) / 128, batch), b(256);
    if (!tb && !acc)      sgemm_k<false, false><<<g, b>>>(A, B, C, M, N, K, lda, ldb, ldc, sA, sB, sC, alpha);
    else if (!tb && acc)  sgemm_k<false, true ><<<g, b>>>(A, B, C, M, N, K, lda, ldb, ldc, sA, sB, sC, alpha);
    else if (tb && !acc)  sgemm_k<true,  false><<<g, b>>>(A, B, C, M, N, K, lda, ldb, ldc, sA, sB, sC, alpha);
    else                  sgemm_k<true,  true ><<<g, b>>>(A, B, C, M, N, K, lda, ldb, ldc, sA, sB, sC, alpha);
}

static void run_attn(float* x, float* outC, bool acc, int S,
                     const float* cs, const float* sn, const float* ln,
                     const float* wq, const float* wk, const float* wv, const float* wo,
                     float* XN, float* Q, float* Kb, float* Vb, float* AO, float* SC)
{
    rmsnorm_k<<<S, 256>>>(x, ln, XN);
    gemm(false, false, XN, wq, Q,  S, D_, D_, D_, D_, D_, 0, 0, 0, 1, 1.f);
    gemm(false, false, XN, wk, Kb, S, D_, D_, D_, D_, D_, 0, 0, 0, 1, 1.f);
    gemm(false, false, XN, wv, Vb, S, D_, D_, D_, D_, D_, 0, 0, 0, 1, 1.f);
    rope_k<<<S, H_ * 32>>>(Q, Kb, cs, sn);
    // scores: per-head Q_h (SxHD, lda=D) @ K_h^T   alpha = 1/sqrt(HD)
    gemm(true, false, Q, Kb, SC, S, S, HD_, D_, D_, S, HD_, HD_, (long long)S * S, H_, 0.125f);
    softmax_causal_k<<<dim3(S, H_), 256>>>(SC, S);
    // PV: per-head P (SxS) @ V_h (SxHD, ldb=D)
    gemm(false, false, SC, Vb, AO, S, HD_, S, S, D_, D_, (long long)S * S, HD_, HD_, H_, 1.f);
    if (acc) gemm(false, true,  AO, wo, x,    S, D_, D_, D_, D_, D_, 0, 0, 0, 1, 1.f);
    else     gemm(false, false, AO, wo, outC, S, D_, D_, D_, D_, D_, 0, 0, 0, 1, 1.f);
}

static void run_ffn(float* x, float* outC, bool acc, int S,
                    const float* ln, const float* w1, const float* w2,
                    float* XN, float* FF)
{
    rmsnorm_k<<<S, 256>>>(x, ln, XN);
    gemm(false, false, XN, w1, FF, S, DFF_, D_, D_, DFF_, DFF_, 0, 0, 0, 1, 1.f);
    gelu_k<<<2048, 256>>>(FF, (long long)S * DFF_);
    if (acc) gemm(false, true,  FF, w2, x,    S, D_, DFF_, DFF_, D_, D_, 0, 0, 0, 1, 1.f);
    else     gemm(false, false, FF, w2, outC, S, D_, DFF_, DFF_, D_, D_, 0, 0, 0, 1, 1.f);
}

// ---------------- entry point ----------------
extern "C" void kernel_launch(void* const* d_in, const int* in_sizes, int n_in,
                              void* d_out, int out_size)
{
    (void)in_sizes; (void)n_in; (void)out_size;
    const int*   ids     = (const int*)  d_in[0];
    const float* embed   = (const float*)d_in[1];
    const float* routerW = (const float*)d_in[2];
    const float* b_aln   = (const float*)d_in[3];
    const float* b_wq    = (const float*)d_in[4];
    const float* b_wk    = (const float*)d_in[5];
    const float* b_wv    = (const float*)d_in[6];
    const float* b_wo    = (const float*)d_in[7];
    const float* b_fln   = (const float*)d_in[8];
    const float* b_w1    = (const float*)d_in[9];
    const float* b_w2    = (const float*)d_in[10];
    const float* a_ln    = (const float*)d_in[11];
    const float* a_wq    = (const float*)d_in[12];
    const float* a_wk    = (const float*)d_in[13];
    const float* a_wv    = (const float*)d_in[14];
    const float* a_wo    = (const float*)d_in[15];
    const float* f_ln    = (const float*)d_in[16];
    const float* f_w1    = (const float*)d_in[17];
    const float* f_w2    = (const float*)d_in[18];
    const float* ln_out  = (const float*)d_in[19];
    float* out = (float*)d_out;

    float* W = nullptr; int* WI = nullptr; double* WD = nullptr;
    cudaGetSymbolAddress((void**)&W,  g_ws);
    cudaGetSymbolAddress((void**)&WI, g_wsi);
    cudaGetSymbolAddress((void**)&WD, g_wsd);

    float *Hh  = W + OFF_H,   *XN  = W + OFF_XN,  *Q   = W + OFF_Q,
          *Kb  = W + OFF_K,   *Vb  = W + OFF_V,   *AO  = W + OFF_AO,
          *FF  = W + OFF_FFN, *SC  = W + OFF_SC,  *XIN = W + OFF_XIN,
          *EOUT= W + OFF_EOUT,*CS  = W + OFF_COS, *SN  = W + OFF_SIN,
          *CSR = W + OFF_COSR,*SNR = W + OFF_SINR,*LG  = W + OFF_LG,
          *RHO = W + OFF_RHO;
    double *PC = WD + OFF_PC, *PS = WD + OFF_PS;
    int *SEL = WI + IOFF_SEL, *STOK = WI + IOFF_STOK, *TSLOT = WI + IOFF_TSLOT,
        *ECNT = WI + IOFF_ECNT, *EOV = WI + IOFF_EOV;

    // rope tables + prefix sums + embedding
    rope_tab_k<<<T_, HD_>>>(CS, SN);
    prefix_k<<<1, HD_>>>(CS, SN, PC, PS);
    embed_k<<<T_, 256>>>(ids, embed, Hh);

    // backbone
    run_attn(Hh, nullptr, true, T_, CS, SN, b_aln, b_wq, b_wk, b_wv, b_wo,
             XN, Q, Kb, Vb, AO, SC);
    run_ffn(Hh, nullptr, true, T_, b_fln, b_w1, b_w2, XN, FF);

    static const int AI[4] = {0, 2, 4, 6};
    static const int FI[4] = {1, 3, 5, 7};

    for (int r = 0; r < NHOPS_; r++) {
        // router logits: h @ router_W[r]^T  (T x 9)
        gemm(true, false, Hh, routerW + (size_t)r * 9 * D_, LG,
             T_, 9, D_, D_, D_, 9, 0, 0, 0, 1, 1.f);
        top2_k<<<(T_ + 255) / 256, 256>>>(LG, SEL, RHO);
        clear_k<<<(9 * CAP_ + 255) / 256, 256>>>(STOK, 9 * CAP_);
        scan_k<<<1, 32>>>(SEL, STOK, TSLOT, ECNT, EOV);
        gather_k<<<8 * CAP_, 256>>>(Hh, STOK, XIN);
        fill_cossin_k<<<8 * CAP_, HD_>>>(STOK, ECNT, EOV, PC, PS, CSR, SNR);

        // attention experts: EOUT[j] = attn_j(xin[AIDX[j]])
        for (int j = 0; j < 4; j++) {
            run_attn(XIN + (size_t)AI[j] * CAP_ * D_,
                     EOUT + (size_t)j * CAP_ * D_, false, CAP_,
                     CSR + (size_t)AI[j] * CAP_ * HD_,
                     SNR + (size_t)AI[j] * CAP_ * HD_,
                     a_ln + (size_t)j * D_,
                     a_wq + (size_t)j * D_ * D_, a_wk + (size_t)j * D_ * D_,
                     a_wv + (size_t)j * D_ * D_, a_wo + (size_t)j * D_ * D_,
                     XN, Q, Kb, Vb, AO, SC);
        }
        // ffn experts: EOUT[4+j] = ffn_j(xin[FIDX[j]])
        for (int j = 0; j < 4; j++) {
            run_ffn(XIN + (size_t)FI[j] * CAP_ * D_,
                    EOUT + (size_t)(4 + j) * CAP_ * D_, false, CAP_,
                    f_ln + (size_t)j * D_,
                    f_w1 + (size_t)j * D_ * DFF_, f_w2 + (size_t)j * DFF_ * D_,
                    XN, FF);
        }

        // h = (1 - rho) * h + combine
        scale_k<<<T_, 256>>>(Hh, RHO);
        combine_k<<<T_, 256>>>(Hh, EOUT, SEL, TSLOT);
    }

    // final: rms(h)*ln_out @ embed^T
    rmsnorm_k<<<T_, 256>>>(Hh, ln_out, XN);
    gemm(true, false, XN, embed, out, T_, V_, D_, D_, D_, V_, 0, 0, 0, 1, 1.f);
}

// round 8
// speedup vs baseline: 2.6216x; 2.6216x over previous
#include <cuda_runtime.h>
#include <math.h>

// ---------------- model constants ----------------
#define D_    1024
#define V_    32000
#define DFF_  4096
#define H_    16
#define T_    2048
#define HD_   64
#define CAP_  512
#define NHOPS_ 4

typedef long long ll;

// ---------------- workspace ----------------
constexpr size_t SZ_TD   = (size_t)T_ * D_;
constexpr size_t OFF_H   = 0;
constexpr size_t OFF_XN  = OFF_H   + SZ_TD;
constexpr size_t OFF_Q   = OFF_XN  + SZ_TD;
constexpr size_t OFF_K   = OFF_Q   + SZ_TD;
constexpr size_t OFF_V   = OFF_K   + SZ_TD;
constexpr size_t OFF_AO  = OFF_V   + SZ_TD;
constexpr size_t OFF_FFN = OFF_AO  + SZ_TD;
constexpr size_t OFF_SC  = OFF_FFN + (size_t)T_ * DFF_;
constexpr size_t OFF_XIN = OFF_SC  + (size_t)H_ * T_ * T_;
constexpr size_t OFF_EOUT= OFF_XIN + (size_t)8 * CAP_ * D_;
constexpr size_t OFF_COS = OFF_EOUT+ (size_t)8 * CAP_ * D_;
constexpr size_t OFF_SIN = OFF_COS + (size_t)T_ * HD_;
constexpr size_t OFF_COSR= OFF_SIN + (size_t)T_ * HD_;
constexpr size_t OFF_SINR= OFF_COSR+ (size_t)8 * CAP_ * HD_;
constexpr size_t OFF_LG  = OFF_SINR+ (size_t)8 * CAP_ * HD_;
constexpr size_t OFF_RHO = OFF_LG  + (size_t)T_ * 9;
constexpr size_t WS_TOTAL= OFF_RHO + (size_t)T_;
__device__ float g_ws[WS_TOTAL];

constexpr size_t OFF_PC = 0;
constexpr size_t OFF_PS = (size_t)(T_ + 1) * HD_;
constexpr size_t WSD_TOTAL = 2 * (size_t)(T_ + 1) * HD_;
__device__ double g_wsd[WSD_TOTAL];

constexpr size_t IOFF_SEL   = 0;
constexpr size_t IOFF_STOK  = IOFF_SEL  + 2 * T_;
constexpr size_t IOFF_TSLOT = IOFF_STOK + 9 * CAP_;
constexpr size_t IOFF_ECNT  = IOFF_TSLOT + 2 * T_;
constexpr size_t IOFF_EOV   = IOFF_ECNT + 9;
constexpr size_t WSI_TOTAL  = IOFF_EOV + 9;
__device__ int g_wsi[WSI_TOTAL];

// ---------------- double-buffered vectorized SGEMM ----------------
// C = alpha * A(MxK) * op(B); TB: B is NxK row-major (C=A*B^T), else KxN.
// Requirements (all call sites conform): M % 128 == 0, K % 16 == 0,
// lda % 4 == 0, ldb % 4 == 0, 16B-aligned base pointers. N arbitrary
// (guarded); for !TB additionally N % 4 == 0 (true at all call sites).
// Two-level batch: z -> (zo = z/inner, zi = z%inner), offsets s*o / s*i.
template<bool TB, bool ACC>
__global__ void __launch_bounds__(256)
sgemm_k(const float* __restrict__ A, const float* __restrict__ B,
        float* __restrict__ C, int M, int N, int K,
        int lda, int ldb, int ldc, int inner,
        ll sAo, ll sBo, ll sCo, ll sAi, ll sBi, ll sCi, float alpha)
{
    __shared__ float As[2][16][128];
    __shared__ float Bs[2][16][128];
    int z = blockIdx.z, zo = z / inner, zi = z % inner;
    A += zo * sAo + zi * sAi;
    B += zo * sBo + zi * sBi;
    C += zo * sCo + zi * sCi;
    int m0 = blockIdx.y * 128, n0 = blockIdx.x * 128;
    int tid = threadIdx.x;
    int tx = tid & 15, ty = tid >> 4;

    // A loader: row = tid&127, two float4 at k-cols (tid>>7) and (tid>>7)+2
    const int arow = tid & 127;
    const int ac4  = tid >> 7;          // 0 or 1
    // B loader (TB): n-row = tid&127, k-cols like A
    // B loader (!TB): k-rows (tid>>5) and +8, n-col4 = (tid&31)*4
    const int bk   = tid >> 5;          // 0..7
    const int bn4  = (tid & 31) * 4;

    float4 pa[2], pb[2];

    auto fetchA = [&](int k0) {
        const float* base = A + (ll)(m0 + arow) * lda + k0;
        pa[0] = *reinterpret_cast<const float4*>(base + ac4 * 4);
        pa[1] = *reinterpret_cast<const float4*>(base + (ac4 + 2) * 4);
    };
    auto storeA = [&](int buf) {
        #pragma unroll
        for (int i = 0; i < 2; i++) {
            int c = (ac4 + i * 2) * 4;
            As[buf][c + 0][arow] = (i ? pa[1].x : pa[0].x);
            As[buf][c + 1][arow] = (i ? pa[1].y : pa[0].y);
            As[buf][c + 2][arow] = (i ? pa[1].z : pa[0].z);
            As[buf][c + 3][arow] = (i ? pa[1].w : pa[0].w);
        }
    };
    auto fetchB = [&](int k0) {
        if (TB) {
            int gn = n0 + arow;
            bool ok = gn < N;
            const float* base = B + (ll)gn * ldb + k0;
            pb[0] = ok ? *reinterpret_cast<const float4*>(base + ac4 * 4)
                       : make_float4(0.f, 0.f, 0.f, 0.f);
            pb[1] = ok ? *reinterpret_cast<const float4*>(base + (ac4 + 2) * 4)
                       : make_float4(0.f, 0.f, 0.f, 0.f);
        } else {
            bool ok = (n0 + bn4) < N;   // N % 4 == 0 at all !TB sites
            #pragma unroll
            for (int i = 0; i < 2; i++) {
                pb[i] = ok ? *reinterpret_cast<const float4*>(
                                 B + (ll)(k0 + bk + i * 8) * ldb + n0 + bn4)
                           : make_float4(0.f, 0.f, 0.f, 0.f);
            }
        }
    };
    auto storeB = [&](int buf) {
        if (TB) {
            #pragma unroll
            for (int i = 0; i < 2; i++) {
                int c = (ac4 + i * 2) * 4;
                Bs[buf][c + 0][arow] = (i ? pb[1].x : pb[0].x);
                Bs[buf][c + 1][arow] = (i ? pb[1].y : pb[0].y);
                Bs[buf][c + 2][arow] = (i ? pb[1].z : pb[0].z);
                Bs[buf][c + 3][arow] = (i ? pb[1].w : pb[0].w);
            }
        } else {
            #pragma unroll
            for (int i = 0; i < 2; i++)
                *reinterpret_cast<float4*>(&Bs[buf][bk + i * 8][bn4]) = pb[i];
        }
    };

    float acc[8][8];
    #pragma unroll
    for (int i = 0; i < 8; i++)
        #pragma unroll
        for (int j = 0; j < 8; j++) acc[i][j] = 0.f;

    int nk = K >> 4;
    fetchA(0); fetchB(0);
    storeA(0); storeB(0);
    __syncthreads();

    for (int kt = 0; kt < nk; kt++) {
        int cur = kt & 1;
        if (kt + 1 < nk) { fetchA((kt + 1) << 4); fetchB((kt + 1) << 4); }
        #pragma unroll
        for (int k = 0; k < 16; k++) {
            float4 a0 = *reinterpret_cast<const float4*>(&As[cur][k][ty * 8]);
            float4 a1 = *reinterpret_cast<const float4*>(&As[cur][k][ty * 8 + 4]);
            float4 b0 = *reinterpret_cast<const float4*>(&Bs[cur][k][tx * 8]);
            float4 b1 = *reinterpret_cast<const float4*>(&Bs[cur][k][tx * 8 + 4]);
            float av[8] = {a0.x, a0.y, a0.z, a0.w, a1.x, a1.y, a1.z, a1.w};
            float bv[8] = {b0.x, b0.y, b0.z, b0.w, b1.x, b1.y, b1.z, b1.w};
            #pragma unroll
            for (int i = 0; i < 8; i++)
                #pragma unroll
                for (int j = 0; j < 8; j++)
                    acc[i][j] += av[i] * bv[j];
        }
        if (kt + 1 < nk) {
            storeA(cur ^ 1); storeB(cur ^ 1);
            __syncthreads();
        }
    }

    #pragma unroll
    for (int i = 0; i < 8; i++) {
        int gm = m0 + ty * 8 + i;
        #pragma unroll
        for (int j = 0; j < 8; j++) {
            int gn = n0 + tx * 8 + j;
            if (gn >= N) continue;
            ll off = (ll)gm * ldc + gn;
            float v = alpha * acc[i][j];
            if (ACC) C[off] += v; else C[off] = v;
        }
    }
}

// ---------------- small kernels ----------------
__global__ void rope_tab_k(float* __restrict__ cs, float* __restrict__ sn)
{
    int t = blockIdx.x, i = threadIdx.x;           // i in [0,64)
    int j = i & 31;
    float ex = (float)(2 * j) / 64.0f;
    float inv = (float)(1.0 / pow(10000.0, (double)ex));
    float ang = (float)t * inv;
    cs[t * HD_ + i] = cosf(ang);
    sn[t * HD_ + i] = sinf(ang);
}

__global__ void prefix_k(const float* __restrict__ cs, const float* __restrict__ sn,
                         double* __restrict__ pc, double* __restrict__ ps)
{
    int d = threadIdx.x;
    double a = 0.0, b = 0.0;
    pc[d] = 0.0; ps[d] = 0.0;
    for (int t = 0; t < T_; t++) {
        a += (double)cs[t * HD_ + d];
        b += (double)sn[t * HD_ + d];
        pc[(t + 1) * HD_ + d] = a;
        ps[(t + 1) * HD_ + d] = b;
    }
}

__global__ void embed_k(const int* __restrict__ ids, const float* __restrict__ em,
                        float* __restrict__ h)
{
    int t = blockIdx.x;
    ll r = ids[t];
    const float* src = em + r * D_;
    float* dst = h + (size_t)t * D_;
    for (int d = threadIdx.x; d < D_; d += 256) dst[d] = src[d];
}

// batched rmsnorm: grid.x = nE*rowsPerE rows; expert e = row / rowsPerE.
__global__ void rmsnorm_b_k(const float* __restrict__ x, const float* __restrict__ ln,
                            float* __restrict__ y, int rowsPerE,
                            ll sxE, int slnE, ll syE)
{
    int row = blockIdx.x;
    int e = row / rowsPerE, r = row % rowsPerE;
    const float* xr = x + e * sxE + (size_t)r * D_;
    const float* lr = ln + e * slnE;
    float* yr = y + e * syE + (size_t)r * D_;
    __shared__ float red[256];
    float s = 0.f;
    for (int d = threadIdx.x; d < D_; d += 256) { float v = xr[d]; s += v * v; }
    red[threadIdx.x] = s; __syncthreads();
    for (int st = 128; st > 0; st >>= 1) {
        if (threadIdx.x < st) red[threadIdx.x] += red[threadIdx.x + st];
        __syncthreads();
    }
    float rr = rsqrtf(red[0] / (float)D_ + 1e-6f);
    for (int d = threadIdx.x; d < D_; d += 256) yr[d] = xr[d] * rr * lr[d];
}

// batched rope: grid.x = total rows; cs row = (row/rowsPerE)*exStride + row%rowsPerE
__global__ void rope_b_k(float* __restrict__ q, float* __restrict__ k,
                         const float* __restrict__ cs, const float* __restrict__ sn,
                         int rowsPerE, int exStride)
{
    int row = blockIdx.x;
    int csRow = (row / rowsPerE) * exStride + (row % rowsPerE);
    int tid = threadIdx.x;                 // 512 = 16 heads * 32
    int h = tid >> 5, i = tid & 31;
    float c1 = cs[csRow * HD_ + i],      s1 = sn[csRow * HD_ + i];
    float c2 = cs[csRow * HD_ + i + 32], s2 = sn[csRow * HD_ + i + 32];
    ll base = (ll)row * D_ + h * HD_ + i;
    float q0 = q[base], q1 = q[base + 32];
    q[base]      = q0 * c1 - q1 * s1;
    q[base + 32] = q1 * c2 + q0 * s2;
    float k0 = k[base], k1 = k[base + 32];
    k[base]      = k0 * c1 - k1 * s1;
    k[base + 32] = k1 * c2 + k0 * s2;
}

__global__ void softmax_causal_k(float* __restrict__ sc, int S)
{
    int i = blockIdx.x, b = blockIdx.y;
    float* row = sc + ((size_t)b * S + i) * (size_t)S;
    int valid = i + 1;
    __shared__ float red[256];
    int tid = threadIdx.x;
    float m = -1e30f;
    for (int j = tid; j < valid; j += 256) m = fmaxf(m, row[j]);
    red[tid] = m; __syncthreads();
    for (int st = 128; st > 0; st >>= 1) {
        if (tid < st) red[tid] = fmaxf(red[tid], red[tid + st]);
        __syncthreads();
    }
    m = red[0]; __syncthreads();
    float sum = 0.f;
    for (int j = tid; j < valid; j += 256) { float e = expf(row[j] - m); row[j] = e; sum += e; }
    red[tid] = sum; __syncthreads();
    for (int st = 128; st > 0; st >>= 1) {
        if (tid < st) red[tid] += red[tid + st];
        __syncthreads();
    }
    float inv = 1.0f / red[0];
    for (int j = tid; j < valid; j += 256) row[j] *= inv;
    for (int j = valid + tid; j < S; j += 256) row[j] = 0.f;
}

__global__ void gelu_k(float* __restrict__ x, ll n)
{
    for (ll i = blockIdx.x * (ll)blockDim.x + threadIdx.x; i < n;
         i += (ll)gridDim.x * blockDim.x) {
        float v = x[i];
        float t = tanhf(0.7978845608028654f * (v + 0.044715f * v * v * v));
        x[i] = 0.5f * v * (1.f + t);
    }
}

__global__ void top2_k(const float* __restrict__ lg, int* __restrict__ sel,
                       float* __restrict__ rho)
{
    int t = blockIdx.x * blockDim.x + threadIdx.x;
    if (t >= T_) return;
    const float* l = lg + (size_t)t * 9;
    int e0 = 0; float b0 = l[0];
    for (int e = 1; e < 9; e++) if (l[e] > b0) { b0 = l[e]; e0 = e; }
    int e1 = -1; float b1 = -1e30f;
    for (int e = 0; e < 9; e++) { if (e == e0) continue; if (l[e] > b1) { b1 = l[e]; e1 = e; } }
    sel[2 * t] = e0; sel[2 * t + 1] = e1;
    rho[t] = 0.5f * (float)((e0 < 8 ? 1 : 0) + (e1 < 8 ? 1 : 0));
}

__global__ void clear_k(int* __restrict__ p, int n)
{
    int i = blockIdx.x * blockDim.x + threadIdx.x;
    if (i < n) p[i] = -1;
}

__global__ void scan_k(const int* __restrict__ sel, int* __restrict__ stok,
                       int* __restrict__ tslot, int* __restrict__ ecnt,
                       int* __restrict__ eov)
{
    int e = threadIdx.x;
    if (e >= 9) return;
    int cnt = 0, ov = T_;
    for (int t = 0; t < T_; t++) {
        #pragma unroll
        for (int j = 0; j < 2; j++) {
            if (sel[2 * t + j] == e) {
                int r = cnt++;
                if (r < CAP_) { stok[e * CAP_ + r] = t; tslot[2 * t + j] = r; }
                else          { tslot[2 * t + j] = -1; if (r == CAP_) ov = t; }
            }
        }
    }
    ecnt[e] = cnt;
    eov[e] = ov;
}

__global__ void gather_k(const float* __restrict__ h, const int* __restrict__ stok,
                         float* __restrict__ xin)
{
    int row = blockIdx.x;                 // 0..8*CAP-1
    int tok = stok[row];
    float* xo = xin + (size_t)row * D_;
    if (tok >= 0) {
        const float* hr = h + (size_t)tok * D_;
        for (int d = threadIdx.x; d < D_; d += 256) xo[d] = 0.5f * hr[d];
    } else {
        for (int d = threadIdx.x; d < D_; d += 256) xo[d] = 0.f;
    }
}

// cos_r/sin_r per the reference's raw-slot einsum (interval prefix sums).
__global__ void fill_cossin_k(const int* __restrict__ stok, const int* __restrict__ ecnt,
                              const int* __restrict__ eov,
                              const double* __restrict__ pc, const double* __restrict__ ps,
                              float* __restrict__ csr, float* __restrict__ snr)
{
    int row = blockIdx.x;               // 8*CAP
    int e = row / CAP_, c = row % CAP_;
    int d = threadIdx.x;                // 64
    int m = ecnt[e];
    int mc = m < CAP_ ? m : CAP_;
    bool active = (c < mc) || (m == 0 && c == 0);
    if (!active) {
        csr[row * HD_ + d] = 0.f;
        snr[row * HD_ + d] = 0.f;
        return;
    }
    int start = (c == 0) ? 0 : stok[e * CAP_ + c];
    int end;
    if (m == 0)            end = T_;
    else if (c + 1 < m)    end = (c + 1 < CAP_) ? stok[e * CAP_ + c + 1] : eov[e];
    else                   end = T_;
    csr[row * HD_ + d] = (float)(pc[end * HD_ + d] - pc[start * HD_ + d]);
    snr[row * HD_ + d] = (float)(ps[end * HD_ + d] - ps[start * HD_ + d]);
}

__global__ void scale_k(float* __restrict__ h, const float* __restrict__ rho)
{
    int t = blockIdx.x;
    float f = 1.0f - rho[t];
    float* hr = h + (size_t)t * D_;
    for (int d = threadIdx.x; d < D_; d += 256) hr[d] *= f;
}

__global__ void combine_k(float* __restrict__ h, const float* __restrict__ eout,
                          const int* __restrict__ sel, const int* __restrict__ tslot)
{
    int t = blockIdx.x;
    float* hr = h + (size_t)t * D_;
    #pragma unroll
    for (int j = 0; j < 2; j++) {
        int e = sel[2 * t + j];
        int s = tslot[2 * t + j];
        if (e < 8 && s >= 0) {
            const float* src = eout + ((size_t)e * CAP_ + s) * D_;
            for (int d = threadIdx.x; d < D_; d += 256) hr[d] += 0.5f * src[d];
        }
    }
}

// ---------------- host GEMM wrapper ----------------
static void gemm(bool tb, bool acc, const float* A, const float* B, float* C,
                 int M, int N, int K, int lda, int ldb, int ldc,
                 int nz, int inner,
                 ll sAo, ll sBo, ll sCo, ll sAi, ll sBi, ll sCi, float alpha)
{
    dim3 g((N + 127) / 128, M / 128, nz), b(256);
    if (!tb && !acc)      sgemm_k<false,false><<<g,b>>>(A,B,C,M,N,K,lda,ldb,ldc,inner,sAo,sBo,sCo,sAi,sBi,sCi,alpha);
    else if (!tb && acc)  sgemm_k<false,true ><<<g,b>>>(A,B,C,M,N,K,lda,ldb,ldc,inner,sAo,sBo,sCo,sAi,sBi,sCi,alpha);
    else if (tb && !acc)  sgemm_k<true ,false><<<g,b>>>(A,B,C,M,N,K,lda,ldb,ldc,inner,sAo,sBo,sCo,sAi,sBi,sCi,alpha);
    else                  sgemm_k<true ,true ><<<g,b>>>(A,B,C,M,N,K,lda,ldb,ldc,inner,sAo,sBo,sCo,sAi,sBi,sCi,alpha);
}

// ---------------- entry point ----------------
extern "C" void kernel_launch(void* const* d_in, const int* in_sizes, int n_in,
                              void* d_out, int out_size)
{
    (void)in_sizes; (void)n_in; (void)out_size;
    const int*   ids     = (const int*)  d_in[0];
    const float* embed   = (const float*)d_in[1];
    const float* routerW = (const float*)d_in[2];
    const float* b_aln   = (const float*)d_in[3];
    const float* b_wq    = (const float*)d_in[4];
    const float* b_wk    = (const float*)d_in[5];
    const float* b_wv    = (const float*)d_in[6];
    const float* b_wo    = (const float*)d_in[7];
    const float* b_fln   = (const float*)d_in[8];
    const float* b_w1    = (const float*)d_in[9];
    const float* b_w2    = (const float*)d_in[10];
    const float* a_ln    = (const float*)d_in[11];
    const float* a_wq    = (const float*)d_in[12];
    const float* a_wk    = (const float*)d_in[13];
    const float* a_wv    = (const float*)d_in[14];
    const float* a_wo    = (const float*)d_in[15];
    const float* f_ln    = (const float*)d_in[16];
    const float* f_w1    = (const float*)d_in[17];
    const float* f_w2    = (const float*)d_in[18];
    const float* ln_out  = (const float*)d_in[19];
    float* out = (float*)d_out;

    float* W = nullptr; int* WI = nullptr; double* WD = nullptr;
    cudaGetSymbolAddress((void**)&W,  g_ws);
    cudaGetSymbolAddress((void**)&WI, g_wsi);
    cudaGetSymbolAddress((void**)&WD, g_wsd);

    float *Hh  = W + OFF_H,   *XN  = W + OFF_XN,  *Q   = W + OFF_Q,
          *Kb  = W + OFF_K,   *Vb  = W + OFF_V,   *AO  = W + OFF_AO,
          *FF  = W + OFF_FFN, *SC  = W + OFF_SC,  *XIN = W + OFF_XIN,
          *EOUT= W + OFF_EOUT,*CS  = W + OFF_COS, *SN  = W + OFF_SIN,
          *CSR = W + OFF_COSR,*SNR = W + OFF_SINR,*LG  = W + OFF_LG,
          *RHO = W + OFF_RHO;
    double *PC = WD + OFF_PC, *PS = WD + OFF_PS;
    int *SEL = WI + IOFF_SEL, *STOK = WI + IOFF_STOK, *TSLOT = WI + IOFF_TSLOT,
        *ECNT = WI + IOFF_ECNT, *EOV = WI + IOFF_EOV;

    const ll CD  = (ll)CAP_ * D_;       // 512*1024
    const ll DD  = (ll)D_ * D_;
    const ll CC  = (ll)CAP_ * CAP_;
    const ll CF  = (ll)CAP_ * DFF_;
    const ll DF  = (ll)D_ * DFF_;

    // rope tables + prefix sums + embedding
    rope_tab_k<<<T_, HD_>>>(CS, SN);
    prefix_k<<<1, HD_>>>(CS, SN, PC, PS);
    embed_k<<<T_, 256>>>(ids, embed, Hh);

    // ---------------- backbone attention (S = T) ----------------
    rmsnorm_b_k<<<T_, 256>>>(Hh, b_aln, XN, T_, 0, 0, 0);
    gemm(false,false, XN, b_wq, Q,  T_, D_, D_, D_, D_, D_, 1,1, 0,0,0, 0,0,0, 1.f);
    gemm(false,false, XN, b_wk, Kb, T_, D_, D_, D_, D_, D_, 1,1, 0,0,0, 0,0,0, 1.f);
    gemm(false,false, XN, b_wv, Vb, T_, D_, D_, D_, D_, D_, 1,1, 0,0,0, 0,0,0, 1.f);
    rope_b_k<<<T_, H_ * 32>>>(Q, Kb, CS, SN, T_, 0);
    gemm(true, false, Q, Kb, SC, T_, T_, HD_, D_, D_, T_,
         H_, H_, 0,0,0, HD_, HD_, (ll)T_ * T_, 0.125f);
    softmax_causal_k<<<dim3(T_, H_), 256>>>(SC, T_);
    gemm(false,false, SC, Vb, AO, T_, HD_, T_, T_, D_, D_,
         H_, H_, 0,0,0, (ll)T_ * T_, HD_, HD_, 1.f);
    gemm(false,true, AO, b_wo, Hh, T_, D_, D_, D_, D_, D_, 1,1, 0,0,0, 0,0,0, 1.f);

    // ---------------- backbone FFN ----------------
    rmsnorm_b_k<<<T_, 256>>>(Hh, b_fln, XN, T_, 0, 0, 0);
    gemm(false,false, XN, b_w1, FF, T_, DFF_, D_, D_, DFF_, DFF_, 1,1, 0,0,0, 0,0,0, 1.f);
    gelu_k<<<2048, 256>>>(FF, (ll)T_ * DFF_);
    gemm(false,true, FF, b_w2, Hh, T_, D_, DFF_, DFF_, D_, D_, 1,1, 0,0,0, 0,0,0, 1.f);

    for (int r = 0; r < NHOPS_; r++) {
        // router logits: h @ router_W[r]^T  (T x 9)
        gemm(true, false, Hh, routerW + (size_t)r * 9 * D_, LG,
             T_, 9, D_, D_, D_, 9, 1,1, 0,0,0, 0,0,0, 1.f);
        top2_k<<<(T_ + 255) / 256, 256>>>(LG, SEL, RHO);
        clear_k<<<(9 * CAP_ + 255) / 256, 256>>>(STOK, 9 * CAP_);
        scan_k<<<1, 32>>>(SEL, STOK, TSLOT, ECNT, EOV);
        gather_k<<<8 * CAP_, 256>>>(Hh, STOK, XIN);
        fill_cossin_k<<<8 * CAP_, HD_>>>(STOK, ECNT, EOV, PC, PS, CSR, SNR);

        // ----- 4 attention experts, batched (module j uses xin[2j]) -----
        // rmsnorm: x stride 2*CAP*D over experts (AIDX = 0,2,4,6)
        rmsnorm_b_k<<<4 * CAP_, 256>>>(XIN, a_ln, XN, CAP_, 2 * CD, D_, CD);
        gemm(false,false, XN, a_wq, Q,  CAP_, D_, D_, D_, D_, D_,
             4,1, CD, DD, CD, 0,0,0, 1.f);
        gemm(false,false, XN, a_wk, Kb, CAP_, D_, D_, D_, D_, D_,
             4,1, CD, DD, CD, 0,0,0, 1.f);
        gemm(false,false, XN, a_wv, Vb, CAP_, D_, D_, D_, D_, D_,
             4,1, CD, DD, CD, 0,0,0, 1.f);
        rope_b_k<<<4 * CAP_, H_ * 32>>>(Q, Kb, CSR, SNR, CAP_, 2 * CAP_);
        // scores: z = expert*16 + head
        gemm(true, false, Q, Kb, SC, CAP_, CAP_, HD_, D_, D_, CAP_,
             4 * H_, H_, CD, CD, 16 * CC, HD_, HD_, CC, 0.125f);
        softmax_causal_k<<<dim3(CAP_, 4 * H_), 256>>>(SC, CAP_);
        gemm(false,false, SC, Vb, AO, CAP_, HD_, CAP_, CAP_, D_, D_,
             4 * H_, H_, 16 * CC, CD, CD, CC, HD_, HD_, 1.f);
        gemm(false,false, AO, a_wo, EOUT, CAP_, D_, D_, D_, D_, D_,
             4,1, CD, DD, CD, 0,0,0, 1.f);

        // ----- 4 FFN experts, batched (module j uses xin[2j+1]) -----
        rmsnorm_b_k<<<4 * CAP_, 256>>>(XIN + CD, f_ln, XN, CAP_, 2 * CD, D_, CD);
        gemm(false,false, XN, f_w1, FF, CAP_, DFF_, D_, D_, DFF_, DFF_,
             4,1, CD, DF, CF, 0,0,0, 1.f);
        gelu_k<<<2048, 256>>>(FF, (ll)4 * CAP_ * DFF_);
        gemm(false,false, FF, f_w2, EOUT + 4 * CD, CAP_, D_, DFF_, DFF_, D_, D_,
             4,1, CF, DF, CD, 0,0,0, 1.f);

        // h = (1 - rho) * h + combine
        scale_k<<<T_, 256>>>(Hh, RHO);
        combine_k<<<T_, 256>>>(Hh, EOUT, SEL, TSLOT);
    }

    // final: rms(h)*ln_out @ embed^T
    rmsnorm_b_k<<<T_, 256>>>(Hh, ln_out, XN, T_, 0, 0, 0);
    gemm(true, false, XN, embed, out, T_, V_, D_, D_, D_, V_,
         1,1, 0,0,0, 0,0,0, 1.f);
}

// round 13
// speedup vs baseline: 2.9601x; 1.1291x over previous
#include <cuda_runtime.h>
#include <cuda_bf16.h>
#include <math.h>
#include <stdint.h>

// ---------------- model constants ----------------
#define D_    1024
#define V_    32000
#define DFF_  4096
#define H_    16
#define T_    2048
#define HD_   64
#define CAP_  512
#define NHOPS_ 4

typedef long long ll;
typedef __nv_bfloat16 bf16;

// ---------------- fp32 workspace (identical to R8) ----------------
constexpr size_t SZ_TD   = (size_t)T_ * D_;
constexpr size_t OFF_H   = 0;
constexpr size_t OFF_XN  = OFF_H   + SZ_TD;
constexpr size_t OFF_Q   = OFF_XN  + SZ_TD;
constexpr size_t OFF_K   = OFF_Q   + SZ_TD;
constexpr size_t OFF_V   = OFF_K   + SZ_TD;
constexpr size_t OFF_AO  = OFF_V   + SZ_TD;
constexpr size_t OFF_FFN = OFF_AO  + SZ_TD;
constexpr size_t OFF_SC  = OFF_FFN + (size_t)T_ * DFF_;
constexpr size_t OFF_XIN = OFF_SC  + (size_t)H_ * T_ * T_;
constexpr size_t OFF_EOUT= OFF_XIN + (size_t)8 * CAP_ * D_;
constexpr size_t OFF_COS = OFF_EOUT+ (size_t)8 * CAP_ * D_;
constexpr size_t OFF_SIN = OFF_COS + (size_t)T_ * HD_;
constexpr size_t OFF_COSR= OFF_SIN + (size_t)T_ * HD_;
constexpr size_t OFF_SINR= OFF_COSR+ (size_t)8 * CAP_ * HD_;
constexpr size_t OFF_LG  = OFF_SINR+ (size_t)8 * CAP_ * HD_;
constexpr size_t OFF_RHO = OFF_LG  + (size_t)T_ * 9;
constexpr size_t WS_TOTAL= OFF_RHO + (size_t)T_;
__device__ float g_ws[WS_TOTAL];

constexpr size_t OFF_PC = 0;
constexpr size_t OFF_PS = (size_t)(T_ + 1) * HD_;
constexpr size_t WSD_TOTAL = 2 * (size_t)(T_ + 1) * HD_;
__device__ double g_wsd[WSD_TOTAL];

constexpr size_t IOFF_SEL   = 0;
constexpr size_t IOFF_STOK  = IOFF_SEL  + 2 * T_;
constexpr size_t IOFF_TSLOT = IOFF_STOK + 9 * CAP_;
constexpr size_t IOFF_ECNT  = IOFF_TSLOT + 2 * T_;
constexpr size_t IOFF_EOV   = IOFF_ECNT + 9;
constexpr size_t WSI_TOTAL  = IOFF_EOV + 9;
__device__ int g_wsi[WSI_TOTAL];

// ---------------- bf16 hi/lo workspace (vocab GEMM only) ----------------
constexpr ll TDc = (ll)T_ * D_;
constexpr ll VDc = (ll)V_ * D_;
constexpr ll BO_XN  = 0;          // rms(h)*ln_out, T x D
constexpr ll BO_EMB = TDc;        // embed, V x D (n-major, k contiguous)
constexpr ll BT2    = TDc + VDc;  // ~35M elems, ~70 MB per array
__device__ bf16 g_bh[BT2];
__device__ bf16 g_bl[BT2];

// ================= bf16 2-way-split tensor GEMM (R9-proven) =================
// C = alpha * (Ah+Al)(m x k, lda) * (Bh+Bl)^T(n x k, ldb), 4 product terms.
// Static smem 49,152 B (exactly the proven R9 envelope).
// Requirements: M % 128 == 0, K % 16 == 0, lda/ldb % 8 == 0, ldc even,
// N arbitrary (even), base pointers 16B aligned.
#define SPITCH 24

__device__ __forceinline__ void ldsm4(uint32_t& r0, uint32_t& r1,
                                      uint32_t& r2, uint32_t& r3, uint32_t a)
{
    asm volatile("ldmatrix.sync.aligned.m8n8.x4.shared.b16 {%0,%1,%2,%3}, [%4];"
                 : "=r"(r0), "=r"(r1), "=r"(r2), "=r"(r3) : "r"(a));
}
__device__ __forceinline__ void mma16816(float* c, const uint32_t* a, const uint32_t* b)
{
    asm volatile("mma.sync.aligned.m16n8k16.row.col.f32.bf16.bf16.f32 "
                 "{%0,%1,%2,%3}, {%4,%5,%6,%7}, {%8,%9}, {%0,%1,%2,%3};"
                 : "+f"(c[0]), "+f"(c[1]), "+f"(c[2]), "+f"(c[3])
                 : "r"(a[0]), "r"(a[1]), "r"(a[2]), "r"(a[3]), "r"(b[0]), "r"(b[1]));
}

__global__ void __launch_bounds__(256)
tgemm_k(const bf16* __restrict__ Ah, const bf16* __restrict__ Al,
        const bf16* __restrict__ Bh, const bf16* __restrict__ Bl,
        float* __restrict__ C, int M, int N, int K,
        int lda, int ldb, int ldc, float alpha)
{
    __shared__ bf16 sA[2][2][128 * SPITCH];
    __shared__ bf16 sB[2][2][128 * SPITCH];
    int m0 = blockIdx.y * 128, n0 = blockIdx.x * 128;
    int tid = threadIdx.x, wid = tid >> 5, lane = tid & 31;
    int wm = (wid & 1) * 64, wn = (wid >> 1) * 32;
    int g = lane >> 2, t4 = lane & 3;

    int lrow = tid >> 1, lkc = (tid & 1) * 8;
    uint4 rah, ral, rbh, rbl;
    auto fetch = [&](int k0) {
        ll ao = (ll)(m0 + lrow) * lda + k0 + lkc;
        rah = *reinterpret_cast<const uint4*>(Ah + ao);
        ral = *reinterpret_cast<const uint4*>(Al + ao);
        int gn = n0 + lrow;
        if (gn < N) {
            ll bo = (ll)gn * ldb + k0 + lkc;
            rbh = *reinterpret_cast<const uint4*>(Bh + bo);
            rbl = *reinterpret_cast<const uint4*>(Bl + bo);
        } else {
            rbh = make_uint4(0, 0, 0, 0); rbl = rbh;
        }
    };
    auto store = [&](int buf) {
        int so = lrow * SPITCH + lkc;
        *reinterpret_cast<uint4*>(&sA[buf][0][so]) = rah;
        *reinterpret_cast<uint4*>(&sA[buf][1][so]) = ral;
        *reinterpret_cast<uint4*>(&sB[buf][0][so]) = rbh;
        *reinterpret_cast<uint4*>(&sB[buf][1][so]) = rbl;
    };

    int mat = lane >> 3, mr = lane & 7;
    int aRow = (mat & 1) * 8 + mr, aCol = (mat >> 1) * 8;
    int bRow = (mat >> 1) * 8 + mr, bCol = (mat & 1) * 8;
    uint32_t aBase = (uint32_t)__cvta_generic_to_shared(&sA[0][0][0]);
    uint32_t bBase = (uint32_t)__cvta_generic_to_shared(&sB[0][0][0]);

    float acc[4][4][4];
    #pragma unroll
    for (int i = 0; i < 4; i++)
        #pragma unroll
        for (int j = 0; j < 4; j++)
            #pragma unroll
            for (int p = 0; p < 4; p++) acc[i][j][p] = 0.f;

    int nk = K >> 4;
    fetch(0); store(0); __syncthreads();

    for (int kt = 0; kt < nk; kt++) {
        int cur = kt & 1;
        if (kt + 1 < nk) fetch((kt + 1) << 4);

        uint32_t ah[4][4], al[4][4], bh[8], bl[8];
        #pragma unroll
        for (int mi = 0; mi < 4; mi++) {
            uint32_t rowoff = (uint32_t)((wm + mi * 16 + aRow) * SPITCH + aCol) * 2;
            ldsm4(ah[mi][0], ah[mi][1], ah[mi][2], ah[mi][3],
                  aBase + (uint32_t)(cur * 2 + 0) * (128 * SPITCH * 2) + rowoff);
            ldsm4(al[mi][0], al[mi][1], al[mi][2], al[mi][3],
                  aBase + (uint32_t)(cur * 2 + 1) * (128 * SPITCH * 2) + rowoff);
        }
        #pragma unroll
        for (int bi = 0; bi < 2; bi++) {
            uint32_t rowoff = (uint32_t)((wn + bi * 16 + bRow) * SPITCH + bCol) * 2;
            ldsm4(bh[bi * 4 + 0], bh[bi * 4 + 1], bh[bi * 4 + 2], bh[bi * 4 + 3],
                  bBase + (uint32_t)(cur * 2 + 0) * (128 * SPITCH * 2) + rowoff);
            ldsm4(bl[bi * 4 + 0], bl[bi * 4 + 1], bl[bi * 4 + 2], bl[bi * 4 + 3],
                  bBase + (uint32_t)(cur * 2 + 1) * (128 * SPITCH * 2) + rowoff);
        }
        #pragma unroll
        for (int mi = 0; mi < 4; mi++)
            #pragma unroll
            for (int ni = 0; ni < 4; ni++) {
                mma16816(acc[mi][ni], ah[mi], &bh[ni * 2]);   // h*h
                mma16816(acc[mi][ni], ah[mi], &bl[ni * 2]);   // h*l
                mma16816(acc[mi][ni], al[mi], &bh[ni * 2]);   // l*h
                mma16816(acc[mi][ni], al[mi], &bl[ni * 2]);   // l*l (4th term)
            }
        if (kt + 1 < nk) { store(cur ^ 1); __syncthreads(); }
    }

    #pragma unroll
    for (int mi = 0; mi < 4; mi++) {
        int r0 = m0 + wm + mi * 16 + g;
        #pragma unroll
        for (int ni = 0; ni < 4; ni++) {
            int col = n0 + wn + ni * 8 + t4 * 2;
            if (col >= N) continue;
            ll o0 = (ll)r0 * ldc + col;
            ll o1 = (ll)(r0 + 8) * ldc + col;
            float2 v0 = make_float2(alpha * acc[mi][ni][0], alpha * acc[mi][ni][1]);
            float2 v1 = make_float2(alpha * acc[mi][ni][2], alpha * acc[mi][ni][3]);
            *reinterpret_cast<float2*>(&C[o0]) = v0;
            *reinterpret_cast<float2*>(&C[o1]) = v1;
        }
    }
}

// 2-way split conversion
__global__ void conv_k(const float* __restrict__ x, bf16* __restrict__ hi,
                       bf16* __restrict__ lo, ll n)
{
    ll stride = (ll)gridDim.x * blockDim.x;
    for (ll i = blockIdx.x * (ll)blockDim.x + threadIdx.x; i < n; i += stride) {
        float v = x[i];
        bf16 h = __float2bfloat16(v);
        hi[i] = h;
        lo[i] = __float2bfloat16(v - __bfloat162float(h));
    }
}

// ---------------- fp32 SGEMM (R8, proven) ----------------
template<bool TB, bool ACC>
__global__ void __launch_bounds__(256)
sgemm_k(const float* __restrict__ A, const float* __restrict__ B,
        float* __restrict__ C, int M, int N, int K,
        int lda, int ldb, int ldc, int inner,
        ll sAo, ll sBo, ll sCo, ll sAi, ll sBi, ll sCi, float alpha)
{
    __shared__ float As[2][16][128];
    __shared__ float Bs[2][16][128];
    int z = blockIdx.z, zo = z / inner, zi = z % inner;
    A += zo * sAo + zi * sAi;
    B += zo * sBo + zi * sBi;
    C += zo * sCo + zi * sCi;
    int m0 = blockIdx.y * 128, n0 = blockIdx.x * 128;
    int tid = threadIdx.x;
    int tx = tid & 15, ty = tid >> 4;
    const int arow = tid & 127;
    const int ac4  = tid >> 7;
    float4 pa[2], pb[2];
    auto fetchA = [&](int k0) {
        const float* base = A + (ll)(m0 + arow) * lda + k0;
        pa[0] = *reinterpret_cast<const float4*>(base + ac4 * 4);
        pa[1] = *reinterpret_cast<const float4*>(base + (ac4 + 2) * 4);
    };
    auto storeA = [&](int buf) {
        #pragma unroll
        for (int i = 0; i < 2; i++) {
            int c = (ac4 + i * 2) * 4;
            As[buf][c + 0][arow] = (i ? pa[1].x : pa[0].x);
            As[buf][c + 1][arow] = (i ? pa[1].y : pa[0].y);
            As[buf][c + 2][arow] = (i ? pa[1].z : pa[0].z);
            As[buf][c + 3][arow] = (i ? pa[1].w : pa[0].w);
        }
    };
    auto fetchB = [&](int k0) {
        if (!TB) {
            bool ok = (n0 + (tid & 31) * 4) < N;
            #pragma unroll
            for (int i = 0; i < 2; i++) {
                pb[i] = ok ? *reinterpret_cast<const float4*>(
                                 B + (ll)(k0 + (tid >> 5) + i * 8) * ldb + n0 + (tid & 31) * 4)
                           : make_float4(0.f, 0.f, 0.f, 0.f);
            }
        } else {
            int gn = n0 + arow;
            bool ok = gn < N;
            const float* base = B + (ll)gn * ldb + k0;
            pb[0] = ok ? *reinterpret_cast<const float4*>(base + ac4 * 4)
                       : make_float4(0.f, 0.f, 0.f, 0.f);
            pb[1] = ok ? *reinterpret_cast<const float4*>(base + (ac4 + 2) * 4)
                       : make_float4(0.f, 0.f, 0.f, 0.f);
        }
    };
    auto storeB = [&](int buf) {
        if (!TB) {
            #pragma unroll
            for (int i = 0; i < 2; i++)
                *reinterpret_cast<float4*>(&Bs[buf][(tid >> 5) + i * 8][(tid & 31) * 4]) = pb[i];
        } else {
            #pragma unroll
            for (int i = 0; i < 2; i++) {
                int c = (ac4 + i * 2) * 4;
                Bs[buf][c + 0][arow] = (i ? pb[1].x : pb[0].x);
                Bs[buf][c + 1][arow] = (i ? pb[1].y : pb[0].y);
                Bs[buf][c + 2][arow] = (i ? pb[1].z : pb[0].z);
                Bs[buf][c + 3][arow] = (i ? pb[1].w : pb[0].w);
            }
        }
    };
    float acc[8][8];
    #pragma unroll
    for (int i = 0; i < 8; i++)
        #pragma unroll
        for (int j = 0; j < 8; j++) acc[i][j] = 0.f;
    int nk = K >> 4;
    fetchA(0); fetchB(0);
    storeA(0); storeB(0);
    __syncthreads();
    for (int kt = 0; kt < nk; kt++) {
        int cur = kt & 1;
        if (kt + 1 < nk) { fetchA((kt + 1) << 4); fetchB((kt + 1) << 4); }
        #pragma unroll
        for (int k = 0; k < 16; k++) {
            float4 a0 = *reinterpret_cast<const float4*>(&As[cur][k][ty * 8]);
            float4 a1 = *reinterpret_cast<const float4*>(&As[cur][k][ty * 8 + 4]);
            float4 b0 = *reinterpret_cast<const float4*>(&Bs[cur][k][tx * 8]);
            float4 b1 = *reinterpret_cast<const float4*>(&Bs[cur][k][tx * 8 + 4]);
            float av[8] = {a0.x, a0.y, a0.z, a0.w, a1.x, a1.y, a1.z, a1.w};
            float bv[8] = {b0.x, b0.y, b0.z, b0.w, b1.x, b1.y, b1.z, b1.w};
            #pragma unroll
            for (int i = 0; i < 8; i++)
                #pragma unroll
                for (int j = 0; j < 8; j++)
                    acc[i][j] += av[i] * bv[j];
        }
        if (kt + 1 < nk) {
            storeA(cur ^ 1); storeB(cur ^ 1);
            __syncthreads();
        }
    }
    #pragma unroll
    for (int i = 0; i < 8; i++) {
        int gm = m0 + ty * 8 + i;
        #pragma unroll
        for (int j = 0; j < 8; j++) {
            int gn = n0 + tx * 8 + j;
            if (gn >= N) continue;
            ll off = (ll)gm * ldc + gn;
            float v = alpha * acc[i][j];
            if (ACC) C[off] += v; else C[off] = v;
        }
    }
}

// ---------------- small kernels (identical to R8) ----------------
__global__ void rope_tab_k(float* __restrict__ cs, float* __restrict__ sn)
{
    int t = blockIdx.x, i = threadIdx.x;
    int j = i & 31;
    float ex = (float)(2 * j) / 64.0f;
    float inv = (float)(1.0 / pow(10000.0, (double)ex));
    float ang = (float)t * inv;
    cs[t * HD_ + i] = cosf(ang);
    sn[t * HD_ + i] = sinf(ang);
}

__global__ void prefix_k(const float* __restrict__ cs, const float* __restrict__ sn,
                         double* __restrict__ pc, double* __restrict__ ps)
{
    int d = threadIdx.x;
    double a = 0.0, b = 0.0;
    pc[d] = 0.0; ps[d] = 0.0;
    for (int t = 0; t < T_; t++) {
        a += (double)cs[t * HD_ + d];
        b += (double)sn[t * HD_ + d];
        pc[(t + 1) * HD_ + d] = a;
        ps[(t + 1) * HD_ + d] = b;
    }
}

__global__ void embed_k(const int* __restrict__ ids, const float* __restrict__ em,
                        float* __restrict__ h)
{
    int t = blockIdx.x;
    ll r = ids[t];
    const float* src = em + r * D_;
    float* dst = h + (size_t)t * D_;
    for (int d = threadIdx.x; d < D_; d += 256) dst[d] = src[d];
}

__global__ void rmsnorm_b_k(const float* __restrict__ x, const float* __restrict__ ln,
                            float* __restrict__ y, int rowsPerE,
                            ll sxE, int slnE, ll syE)
{
    int row = blockIdx.x;
    int e = row / rowsPerE, r = row % rowsPerE;
    const float* xr = x + e * sxE + (size_t)r * D_;
    const float* lr = ln + e * slnE;
    float* yr = y + e * syE + (size_t)r * D_;
    __shared__ float red[256];
    float s = 0.f;
    for (int d = threadIdx.x; d < D_; d += 256) { float v = xr[d]; s += v * v; }
    red[threadIdx.x] = s; __syncthreads();
    for (int st = 128; st > 0; st >>= 1) {
        if (threadIdx.x < st) red[threadIdx.x] += red[threadIdx.x + st];
        __syncthreads();
    }
    float rr = rsqrtf(red[0] / (float)D_ + 1e-6f);
    for (int d = threadIdx.x; d < D_; d += 256) yr[d] = xr[d] * rr * lr[d];
}

__global__ void rope_b_k(float* __restrict__ q, float* __restrict__ k,
                         const float* __restrict__ cs, const float* __restrict__ sn,
                         int rowsPerE, int exStride)
{
    int row = blockIdx.x;
    int csRow = (row / rowsPerE) * exStride + (row % rowsPerE);
    int tid = threadIdx.x;
    int h = tid >> 5, i = tid & 31;
    float c1 = cs[csRow * HD_ + i],      s1 = sn[csRow * HD_ + i];
    float c2 = cs[csRow * HD_ + i + 32], s2 = sn[csRow * HD_ + i + 32];
    ll base = (ll)row * D_ + h * HD_ + i;
    float q0 = q[base], q1 = q[base + 32];
    q[base]      = q0 * c1 - q1 * s1;
    q[base + 32] = q1 * c2 + q0 * s2;
    float k0 = k[base], k1 = k[base + 32];
    k[base]      = k0 * c1 - k1 * s1;
    k[base + 32] = k1 * c2 + k0 * s2;
}

__global__ void softmax_causal_k(float* __restrict__ sc, int S)
{
    int i = blockIdx.x, b = blockIdx.y;
    float* row = sc + ((size_t)b * S + i) * (size_t)S;
    int valid = i + 1;
    __shared__ float red[256];
    int tid = threadIdx.x;
    float m = -1e30f;
    for (int j = tid; j < valid; j += 256) m = fmaxf(m, row[j]);
    red[tid] = m; __syncthreads();
    for (int st = 128; st > 0; st >>= 1) {
        if (tid < st) red[tid] = fmaxf(red[tid], red[tid + st]);
        __syncthreads();
    }
    m = red[0]; __syncthreads();
    float sum = 0.f;
    for (int j = tid; j < valid; j += 256) { float e = expf(row[j] - m); row[j] = e; sum += e; }
    red[tid] = sum; __syncthreads();
    for (int st = 128; st > 0; st >>= 1) {
        if (tid < st) red[tid] += red[tid + st];
        __syncthreads();
    }
    float inv = 1.0f / red[0];
    for (int j = tid; j < valid; j += 256) row[j] *= inv;
    for (int j = valid + tid; j < S; j += 256) row[j] = 0.f;
}

__global__ void gelu_k(float* __restrict__ x, ll n)
{
    for (ll i = blockIdx.x * (ll)blockDim.x + threadIdx.x; i < n;
         i += (ll)gridDim.x * blockDim.x) {
        float v = x[i];
        float t = tanhf(0.7978845608028654f * (v + 0.044715f * v * v * v));
        x[i] = 0.5f * v * (1.f + t);
    }
}

__global__ void top2_k(const float* __restrict__ lg, int* __restrict__ sel,
                       float* __restrict__ rho)
{
    int t = blockIdx.x * blockDim.x + threadIdx.x;
    if (t >= T_) return;
    const float* l = lg + (size_t)t * 9;
    int e0 = 0; float b0 = l[0];
    for (int e = 1; e < 9; e++) if (l[e] > b0) { b0 = l[e]; e0 = e; }
    int e1 = -1; float b1 = -1e30f;
    for (int e = 0; e < 9; e++) { if (e == e0) continue; if (l[e] > b1) { b1 = l[e]; e1 = e; } }
    sel[2 * t] = e0; sel[2 * t + 1] = e1;
    rho[t] = 0.5f * (float)((e0 < 8 ? 1 : 0) + (e1 < 8 ? 1 : 0));
}

__global__ void clear_k(int* __restrict__ p, int n)
{
    int i = blockIdx.x * blockDim.x + threadIdx.x;
    if (i < n) p[i] = -1;
}

__global__ void scan_k(const int* __restrict__ sel, int* __restrict__ stok,
                       int* __restrict__ tslot, int* __restrict__ ecnt,
                       int* __restrict__ eov)
{
    int e = threadIdx.x;
    if (e >= 9) return;
    int cnt = 0, ov = T_;
    for (int t = 0; t < T_; t++) {
        #pragma unroll
        for (int j = 0; j < 2; j++) {
            if (sel[2 * t + j] == e) {
                int r = cnt++;
                if (r < CAP_) { stok[e * CAP_ + r] = t; tslot[2 * t + j] = r; }
                else          { tslot[2 * t + j] = -1; if (r == CAP_) ov = t; }
            }
        }
    }
    ecnt[e] = cnt;
    eov[e] = ov;
}

__global__ void gather_k(const float* __restrict__ h, const int* __restrict__ stok,
                         float* __restrict__ xin)
{
    int row = blockIdx.x;
    int tok = stok[row];
    float* xo = xin + (size_t)row * D_;
    if (tok >= 0) {
        const float* hr = h + (size_t)tok * D_;
        for (int d = threadIdx.x; d < D_; d += 256) xo[d] = 0.5f * hr[d];
    } else {
        for (int d = threadIdx.x; d < D_; d += 256) xo[d] = 0.f;
    }
}

__global__ void fill_cossin_k(const int* __restrict__ stok, const int* __restrict__ ecnt,
                              const int* __restrict__ eov,
                              const double* __restrict__ pc, const double* __restrict__ ps,
                              float* __restrict__ csr, float* __restrict__ snr)
{
    int row = blockIdx.x;
    int e = row / CAP_, c = row % CAP_;
    int d = threadIdx.x;
    int m = ecnt[e];
    int mc = m < CAP_ ? m : CAP_;
    bool active = (c < mc) || (m == 0 && c == 0);
    if (!active) {
        csr[row * HD_ + d] = 0.f;
        snr[row * HD_ + d] = 0.f;
        return;
    }
    int start = (c == 0) ? 0 : stok[e * CAP_ + c];
    int end;
    if (m == 0)            end = T_;
    else if (c + 1 < m)    end = (c + 1 < CAP_) ? stok[e * CAP_ + c + 1] : eov[e];
    else                   end = T_;
    csr[row * HD_ + d] = (float)(pc[end * HD_ + d] - pc[start * HD_ + d]);
    snr[row * HD_ + d] = (float)(ps[end * HD_ + d] - ps[start * HD_ + d]);
}

__global__ void scale_k(float* __restrict__ h, const float* __restrict__ rho)
{
    int t = blockIdx.x;
    float f = 1.0f - rho[t];
    float* hr = h + (size_t)t * D_;
    for (int d = threadIdx.x; d < D_; d += 256) hr[d] *= f;
}

__global__ void combine_k(float* __restrict__ h, const float* __restrict__ eout,
                          const int* __restrict__ sel, const int* __restrict__ tslot)
{
    int t = blockIdx.x;
    float* hr = h + (size_t)t * D_;
    #pragma unroll
    for (int j = 0; j < 2; j++) {
        int e = sel[2 * t + j];
        int s = tslot[2 * t + j];
        if (e < 8 && s >= 0) {
            const float* src = eout + ((size_t)e * CAP_ + s) * D_;
            for (int d = threadIdx.x; d < D_; d += 256) hr[d] += 0.5f * src[d];
        }
    }
}

// ---------------- host GEMM wrapper (R8) ----------------
static void gemm(bool tb, bool acc, const float* A, const float* B, float* C,
                 int M, int N, int K, int lda, int ldb, int ldc,
                 int nz, int inner,
                 ll sAo, ll sBo, ll sCo, ll sAi, ll sBi, ll sCi, float alpha)
{
    dim3 g((N + 127) / 128, M / 128, nz), b(256);
    if (!tb && !acc)      sgemm_k<false,false><<<g,b>>>(A,B,C,M,N,K,lda,ldb,ldc,inner,sAo,sBo,sCo,sAi,sBi,sCi,alpha);
    else if (!tb && acc)  sgemm_k<false,true ><<<g,b>>>(A,B,C,M,N,K,lda,ldb,ldc,inner,sAo,sBo,sCo,sAi,sBi,sCi,alpha);
    else if (tb && !acc)  sgemm_k<true ,false><<<g,b>>>(A,B,C,M,N,K,lda,ldb,ldc,inner,sAo,sBo,sCo,sAi,sBi,sCi,alpha);
    else                  sgemm_k<true ,true ><<<g,b>>>(A,B,C,M,N,K,lda,ldb,ldc,inner,sAo,sBo,sCo,sAi,sBi,sCi,alpha);
}

// ---------------- entry point ----------------
extern "C" void kernel_launch(void* const* d_in, const int* in_sizes, int n_in,
                              void* d_out, int out_size)
{
    (void)in_sizes; (void)n_in; (void)out_size;
    const int*   ids     = (const int*)  d_in[0];
    const float* embed   = (const float*)d_in[1];
    const float* routerW = (const float*)d_in[2];
    const float* b_aln   = (const float*)d_in[3];
    const float* b_wq    = (const float*)d_in[4];
    const float* b_wk    = (const float*)d_in[5];
    const float* b_wv    = (const float*)d_in[6];
    const float* b_wo    = (const float*)d_in[7];
    const float* b_fln   = (const float*)d_in[8];
    const float* b_w1    = (const float*)d_in[9];
    const float* b_w2    = (const float*)d_in[10];
    const float* a_ln    = (const float*)d_in[11];
    const float* a_wq    = (const float*)d_in[12];
    const float* a_wk    = (const float*)d_in[13];
    const float* a_wv    = (const float*)d_in[14];
    const float* a_wo    = (const float*)d_in[15];
    const float* f_ln    = (const float*)d_in[16];
    const float* f_w1    = (const float*)d_in[17];
    const float* f_w2    = (const float*)d_in[18];
    const float* ln_out  = (const float*)d_in[19];
    float* out = (float*)d_out;

    float* W = nullptr; int* WI = nullptr; double* WD = nullptr;
    bf16 *BH = nullptr, *BL = nullptr;
    cudaGetSymbolAddress((void**)&W,  g_ws);
    cudaGetSymbolAddress((void**)&WI, g_wsi);
    cudaGetSymbolAddress((void**)&WD, g_wsd);
    cudaGetSymbolAddress((void**)&BH, g_bh);
    cudaGetSymbolAddress((void**)&BL, g_bl);

    float *Hh  = W + OFF_H,   *XN  = W + OFF_XN,  *Q   = W + OFF_Q,
          *Kb  = W + OFF_K,   *Vb  = W + OFF_V,   *AO  = W + OFF_AO,
          *FF  = W + OFF_FFN, *SC  = W + OFF_SC,  *XIN = W + OFF_XIN,
          *EOUT= W + OFF_EOUT,*CS  = W + OFF_COS, *SN  = W + OFF_SIN,
          *CSR = W + OFF_COSR,*SNR = W + OFF_SINR,*LG  = W + OFF_LG,
          *RHO = W + OFF_RHO;
    double *PC = WD + OFF_PC, *PS = WD + OFF_PS;
    int *SEL = WI + IOFF_SEL, *STOK = WI + IOFF_STOK, *TSLOT = WI + IOFF_TSLOT,
        *ECNT = WI + IOFF_ECNT, *EOV = WI + IOFF_EOV;

    const ll CD  = (ll)CAP_ * D_;
    const ll DD  = (ll)D_ * D_;
    const ll CC  = (ll)CAP_ * CAP_;
    const ll CF  = (ll)CAP_ * DFF_;
    const ll DF  = (ll)D_ * DFF_;

    // convert embed (V x D) to bf16 hi/lo once, for the vocab tensor GEMM
    conv_k<<<4096, 256>>>(embed, BH + BO_EMB, BL + BO_EMB, VDc);

    // rope tables + prefix sums + embedding
    rope_tab_k<<<T_, HD_>>>(CS, SN);
    prefix_k<<<1, HD_>>>(CS, SN, PC, PS);
    embed_k<<<T_, 256>>>(ids, embed, Hh);

    // ---------------- backbone attention (S = T) ----------------
    rmsnorm_b_k<<<T_, 256>>>(Hh, b_aln, XN, T_, 0, 0, 0);
    gemm(false,false, XN, b_wq, Q,  T_, D_, D_, D_, D_, D_, 1,1, 0,0,0, 0,0,0, 1.f);
    gemm(false,false, XN, b_wk, Kb, T_, D_, D_, D_, D_, D_, 1,1, 0,0,0, 0,0,0, 1.f);
    gemm(false,false, XN, b_wv, Vb, T_, D_, D_, D_, D_, D_, 1,1, 0,0,0, 0,0,0, 1.f);
    rope_b_k<<<T_, H_ * 32>>>(Q, Kb, CS, SN, T_, 0);
    gemm(true, false, Q, Kb, SC, T_, T_, HD_, D_, D_, T_,
         H_, H_, 0,0,0, HD_, HD_, (ll)T_ * T_, 0.125f);
    softmax_causal_k<<<dim3(T_, H_), 256>>>(SC, T_);
    gemm(false,false, SC, Vb, AO, T_, HD_, T_, T_, D_, D_,
         H_, H_, 0,0,0, (ll)T_ * T_, HD_, HD_, 1.f);
    gemm(false,true, AO, b_wo, Hh, T_, D_, D_, D_, D_, D_, 1,1, 0,0,0, 0,0,0, 1.f);

    // ---------------- backbone FFN ----------------
    rmsnorm_b_k<<<T_, 256>>>(Hh, b_fln, XN, T_, 0, 0, 0);
    gemm(false,false, XN, b_w1, FF, T_, DFF_, D_, D_, DFF_, DFF_, 1,1, 0,0,0, 0,0,0, 1.f);
    gelu_k<<<2048, 256>>>(FF, (ll)T_ * DFF_);
    gemm(false,true, FF, b_w2, Hh, T_, D_, DFF_, DFF_, D_, D_, 1,1, 0,0,0, 0,0,0, 1.f);

    for (int r = 0; r < NHOPS_; r++) {
        gemm(true, false, Hh, routerW + (size_t)r * 9 * D_, LG,
             T_, 9, D_, D_, D_, 9, 1,1, 0,0,0, 0,0,0, 1.f);
        top2_k<<<(T_ + 255) / 256, 256>>>(LG, SEL, RHO);
        clear_k<<<(9 * CAP_ + 255) / 256, 256>>>(STOK, 9 * CAP_);
        scan_k<<<1, 32>>>(SEL, STOK, TSLOT, ECNT, EOV);
        gather_k<<<8 * CAP_, 256>>>(Hh, STOK, XIN);
        fill_cossin_k<<<8 * CAP_, HD_>>>(STOK, ECNT, EOV, PC, PS, CSR, SNR);

        // ----- 4 attention experts, batched (module j uses xin[2j]) -----
        rmsnorm_b_k<<<4 * CAP_, 256>>>(XIN, a_ln, XN, CAP_, 2 * CD, D_, CD);
        gemm(false,false, XN, a_wq, Q,  CAP_, D_, D_, D_, D_, D_,
             4,1, CD, DD, CD, 0,0,0, 1.f);
        gemm(false,false, XN, a_wk, Kb, CAP_, D_, D_, D_, D_, D_,
             4,1, CD, DD, CD, 0,0,0, 1.f);
        gemm(false,false, XN, a_wv, Vb, CAP_, D_, D_, D_, D_, D_,
             4,1, CD, DD, CD, 0,0,0, 1.f);
        rope_b_k<<<4 * CAP_, H_ * 32>>>(Q, Kb, CSR, SNR, CAP_, 2 * CAP_);
        gemm(true, false, Q, Kb, SC, CAP_, CAP_, HD_, D_, D_, CAP_,
             4 * H_, H_, CD, CD, 16 * CC, HD_, HD_, CC, 0.125f);
        softmax_causal_k<<<dim3(CAP_, 4 * H_), 256>>>(SC, CAP_);
        gemm(false,false, SC, Vb, AO, CAP_, HD_, CAP_, CAP_, D_, D_,
             4 * H_, H_, 16 * CC, CD, CD, CC, HD_, HD_, 1.f);
        gemm(false,false, AO, a_wo, EOUT, CAP_, D_, D_, D_, D_, D_,
             4,1, CD, DD, CD, 0,0,0, 1.f);

        // ----- 4 FFN experts, batched (module j uses xin[2j+1]) -----
        rmsnorm_b_k<<<4 * CAP_, 256>>>(XIN + CD, f_ln, XN, CAP_, 2 * CD, D_, CD);
        gemm(false,false, XN, f_w1, FF, CAP_, DFF_, D_, D_, DFF_, DFF_,
             4,1, CD, DF, CF, 0,0,0, 1.f);
        gelu_k<<<2048, 256>>>(FF, (ll)4 * CAP_ * DFF_);
        gemm(false,false, FF, f_w2, EOUT + 4 * CD, CAP_, D_, DFF_, DFF_, D_, D_,
             4,1, CF, DF, CD, 0,0,0, 1.f);

        scale_k<<<T_, 256>>>(Hh, RHO);
        combine_k<<<T_, 256>>>(Hh, EOUT, SEL, TSLOT);
    }

    // final: rms(h)*ln_out @ embed^T  — bf16 2-way 4-term tensor GEMM
    rmsnorm_b_k<<<T_, 256>>>(Hh, ln_out, XN, T_, 0, 0, 0);
    conv_k<<<2048, 256>>>(XN, BH + BO_XN, BL + BO_XN, TDc);
    {
        dim3 g(V_ / 128, T_ / 128, 1), b(256);
        tgemm_k<<<g, b>>>(BH + BO_XN, BL + BO_XN, BH + BO_EMB, BL + BO_EMB,
                          out, T_, V_, D_, D_, D_, V_, 1.f);
    }
}

// round 14
// speedup vs baseline: 3.1766x; 1.0732x over previous
#include <cuda_runtime.h>
#include <cuda_bf16.h>
#include <math.h>
#include <stdint.h>

// ---------------- model constants ----------------
#define D_    1024
#define V_    32000
#define DFF_  4096
#define H_    16
#define T_    2048
#define HD_   64
#define CAP_  512
#define NHOPS_ 4

typedef long long ll;
typedef __nv_bfloat16 bf16;

// ---------------- fp32 workspace (identical to R8/R13) ----------------
constexpr size_t SZ_TD   = (size_t)T_ * D_;
constexpr size_t OFF_H   = 0;
constexpr size_t OFF_XN  = OFF_H   + SZ_TD;
constexpr size_t OFF_Q   = OFF_XN  + SZ_TD;
constexpr size_t OFF_K   = OFF_Q   + SZ_TD;
constexpr size_t OFF_V   = OFF_K   + SZ_TD;
constexpr size_t OFF_AO  = OFF_V   + SZ_TD;
constexpr size_t OFF_FFN = OFF_AO  + SZ_TD;
constexpr size_t OFF_SC  = OFF_FFN + (size_t)T_ * DFF_;
constexpr size_t OFF_XIN = OFF_SC  + (size_t)H_ * T_ * T_;
constexpr size_t OFF_EOUT= OFF_XIN + (size_t)8 * CAP_ * D_;
constexpr size_t OFF_COS = OFF_EOUT+ (size_t)8 * CAP_ * D_;
constexpr size_t OFF_SIN = OFF_COS + (size_t)T_ * HD_;
constexpr size_t OFF_COSR= OFF_SIN + (size_t)T_ * HD_;
constexpr size_t OFF_SINR= OFF_COSR+ (size_t)8 * CAP_ * HD_;
constexpr size_t OFF_LG  = OFF_SINR+ (size_t)8 * CAP_ * HD_;
constexpr size_t OFF_RHO = OFF_LG  + (size_t)T_ * 9;
constexpr size_t WS_TOTAL= OFF_RHO + (size_t)T_;
__device__ float g_ws[WS_TOTAL];

constexpr size_t OFF_PC = 0;
constexpr size_t OFF_PS = (size_t)(T_ + 1) * HD_;
constexpr size_t WSD_TOTAL = 2 * (size_t)(T_ + 1) * HD_;
__device__ double g_wsd[WSD_TOTAL];

constexpr size_t IOFF_SEL   = 0;
constexpr size_t IOFF_STOK  = IOFF_SEL  + 2 * T_;
constexpr size_t IOFF_TSLOT = IOFF_STOK + 9 * CAP_;
constexpr size_t IOFF_ECNT  = IOFF_TSLOT + 2 * T_;
constexpr size_t IOFF_EOV   = IOFF_ECNT + 9;
constexpr size_t WSI_TOTAL  = IOFF_EOV + 9;
__device__ int g_wsi[WSI_TOTAL];

// ---------------- bf16 hi/lo workspace ----------------
constexpr ll TDc = (ll)T_ * D_;
constexpr ll DDc = (ll)D_ * D_;
constexpr ll DFc = (ll)D_ * DFF_;
constexpr ll VDc = (ll)V_ * D_;
constexpr ll CDc = (ll)CAP_ * D_;
constexpr ll CCc = (ll)CAP_ * CAP_;
constexpr ll CFc = (ll)CAP_ * DFF_;

constexpr ll BO_XN  = 0;                    // 4*CAP*D = T*D
constexpr ll BO_Q   = BO_XN + TDc;
constexpr ll BO_K   = BO_Q  + TDc;          // must stay = BO_Q + TDc (contig conv)
constexpr ll BO_VT  = BO_K  + TDc;
constexpr ll BO_AO  = BO_VT + TDc;
constexpr ll BO_FF  = BO_AO + TDc;          // 4*CAP*DFF
constexpr ll BO_SC  = BO_FF + (ll)4 * CFc;  // 4*H*CAP*CAP = 16.8M
constexpr ll BO_AWQ = BO_SC + (ll)4 * H_ * CCc;
constexpr ll BO_AWK = BO_AWQ + 4 * DDc;
constexpr ll BO_AWV = BO_AWK + 4 * DDc;
constexpr ll BO_AWO = BO_AWV + 4 * DDc;
constexpr ll BO_FW1 = BO_AWO + 4 * DDc;
constexpr ll BO_FW2 = BO_FW1 + 4 * DFc;
constexpr ll BO_XNO = BO_FW2 + 4 * DFc;     // final rms(h)*ln_out, T x D
constexpr ll BO_EMB = BO_XNO + TDc;
constexpr ll BT2    = BO_EMB + VDc;
__device__ bf16 g_bh[BT2];
__device__ bf16 g_bl[BT2];

// ================= bf16 2-way-split tensor GEMMs =================
// 4 product terms: exact product of rounded operands; rep error ~2^-18.
#define SPITCH 24

__device__ __forceinline__ void ldsm4(uint32_t& r0, uint32_t& r1,
                                      uint32_t& r2, uint32_t& r3, uint32_t a)
{
    asm volatile("ldmatrix.sync.aligned.m8n8.x4.shared.b16 {%0,%1,%2,%3}, [%4];"
                 : "=r"(r0), "=r"(r1), "=r"(r2), "=r"(r3) : "r"(a));
}
__device__ __forceinline__ void mma16816(float* c, const uint32_t* a, const uint32_t* b)
{
    asm volatile("mma.sync.aligned.m16n8k16.row.col.f32.bf16.bf16.f32 "
                 "{%0,%1,%2,%3}, {%4,%5,%6,%7}, {%8,%9}, {%0,%1,%2,%3};"
                 : "+f"(c[0]), "+f"(c[1]), "+f"(c[2]), "+f"(c[3])
                 : "r"(a[0]), "r"(a[1]), "r"(a[2]), "r"(a[3]), "r"(b[0]), "r"(b[1]));
}

// ---- non-batched (R13-proven) — vocab GEMM only ----
__global__ void __launch_bounds__(256)
tgemm_k(const bf16* __restrict__ Ah, const bf16* __restrict__ Al,
        const bf16* __restrict__ Bh, const bf16* __restrict__ Bl,
        float* __restrict__ C, int M, int N, int K,
        int lda, int ldb, int ldc, float alpha)
{
    __shared__ bf16 sA[2][2][128 * SPITCH];
    __shared__ bf16 sB[2][2][128 * SPITCH];
    int m0 = blockIdx.y * 128, n0 = blockIdx.x * 128;
    int tid = threadIdx.x, wid = tid >> 5, lane = tid & 31;
    int wm = (wid & 1) * 64, wn = (wid >> 1) * 32;
    int g = lane >> 2, t4 = lane & 3;

    int lrow = tid >> 1, lkc = (tid & 1) * 8;
    uint4 rah, ral, rbh, rbl;
    auto fetch = [&](int k0) {
        ll ao = (ll)(m0 + lrow) * lda + k0 + lkc;
        rah = *reinterpret_cast<const uint4*>(Ah + ao);
        ral = *reinterpret_cast<const uint4*>(Al + ao);
        int gn = n0 + lrow;
        if (gn < N) {
            ll bo = (ll)gn * ldb + k0 + lkc;
            rbh = *reinterpret_cast<const uint4*>(Bh + bo);
            rbl = *reinterpret_cast<const uint4*>(Bl + bo);
        } else {
            rbh = make_uint4(0, 0, 0, 0); rbl = rbh;
        }
    };
    auto store = [&](int buf) {
        int so = lrow * SPITCH + lkc;
        *reinterpret_cast<uint4*>(&sA[buf][0][so]) = rah;
        *reinterpret_cast<uint4*>(&sA[buf][1][so]) = ral;
        *reinterpret_cast<uint4*>(&sB[buf][0][so]) = rbh;
        *reinterpret_cast<uint4*>(&sB[buf][1][so]) = rbl;
    };

    int mat = lane >> 3, mr = lane & 7;
    int aRow = (mat & 1) * 8 + mr, aCol = (mat >> 1) * 8;
    int bRow = (mat >> 1) * 8 + mr, bCol = (mat & 1) * 8;
    uint32_t aBase = (uint32_t)__cvta_generic_to_shared(&sA[0][0][0]);
    uint32_t bBase = (uint32_t)__cvta_generic_to_shared(&sB[0][0][0]);

    float acc[4][4][4];
    #pragma unroll
    for (int i = 0; i < 4; i++)
        #pragma unroll
        for (int j = 0; j < 4; j++)
            #pragma unroll
            for (int p = 0; p < 4; p++) acc[i][j][p] = 0.f;

    int nk = K >> 4;
    fetch(0); store(0); __syncthreads();

    for (int kt = 0; kt < nk; kt++) {
        int cur = kt & 1;
        if (kt + 1 < nk) fetch((kt + 1) << 4);

        uint32_t ah[4][4], al[4][4], bh[8], bl[8];
        #pragma unroll
        for (int mi = 0; mi < 4; mi++) {
            uint32_t rowoff = (uint32_t)((wm + mi * 16 + aRow) * SPITCH + aCol) * 2;
            ldsm4(ah[mi][0], ah[mi][1], ah[mi][2], ah[mi][3],
                  aBase + (uint32_t)(cur * 2 + 0) * (128 * SPITCH * 2) + rowoff);
            ldsm4(al[mi][0], al[mi][1], al[mi][2], al[mi][3],
                  aBase + (uint32_t)(cur * 2 + 1) * (128 * SPITCH * 2) + rowoff);
        }
        #pragma unroll
        for (int bi = 0; bi < 2; bi++) {
            uint32_t rowoff = (uint32_t)((wn + bi * 16 + bRow) * SPITCH + bCol) * 2;
            ldsm4(bh[bi * 4 + 0], bh[bi * 4 + 1], bh[bi * 4 + 2], bh[bi * 4 + 3],
                  bBase + (uint32_t)(cur * 2 + 0) * (128 * SPITCH * 2) + rowoff);
            ldsm4(bl[bi * 4 + 0], bl[bi * 4 + 1], bl[bi * 4 + 2], bl[bi * 4 + 3],
                  bBase + (uint32_t)(cur * 2 + 1) * (128 * SPITCH * 2) + rowoff);
        }
        #pragma unroll
        for (int mi = 0; mi < 4; mi++)
            #pragma unroll
            for (int ni = 0; ni < 4; ni++) {
                mma16816(acc[mi][ni], ah[mi], &bh[ni * 2]);
                mma16816(acc[mi][ni], ah[mi], &bl[ni * 2]);
                mma16816(acc[mi][ni], al[mi], &bh[ni * 2]);
                mma16816(acc[mi][ni], al[mi], &bl[ni * 2]);
            }
        if (kt + 1 < nk) { store(cur ^ 1); __syncthreads(); }
    }

    #pragma unroll
    for (int mi = 0; mi < 4; mi++) {
        int r0 = m0 + wm + mi * 16 + g;
        #pragma unroll
        for (int ni = 0; ni < 4; ni++) {
            int col = n0 + wn + ni * 8 + t4 * 2;
            if (col >= N) continue;
            ll o0 = (ll)r0 * ldc + col;
            ll o1 = (ll)(r0 + 8) * ldc + col;
            *reinterpret_cast<float2*>(&C[o0]) =
                make_float2(alpha * acc[mi][ni][0], alpha * acc[mi][ni][1]);
            *reinterpret_cast<float2*>(&C[o1]) =
                make_float2(alpha * acc[mi][ni][2], alpha * acc[mi][ni][3]);
        }
    }
}

// ---- batched (R9-proven structure + l*l term) — hop-4 expert GEMMs ----
__global__ void __launch_bounds__(256)
tgemm_b_k(const bf16* __restrict__ Ah, const bf16* __restrict__ Al,
          const bf16* __restrict__ Bh, const bf16* __restrict__ Bl,
          float* __restrict__ C, int M, int N, int K,
          int lda, int ldb, int ldc, int inner,
          ll sAo, ll sBo, ll sCo, ll sAi, ll sBi, ll sCi, float alpha)
{
    __shared__ bf16 sA[2][2][128 * SPITCH];
    __shared__ bf16 sB[2][2][128 * SPITCH];
    int z = blockIdx.z, zo = z / inner, zi = z % inner;
    ll aoff = zo * sAo + zi * sAi, boff = zo * sBo + zi * sBi;
    Ah += aoff; Al += aoff;
    Bh += boff; Bl += boff;
    C  += zo * sCo + zi * sCi;
    int m0 = blockIdx.y * 128, n0 = blockIdx.x * 128;
    int tid = threadIdx.x, wid = tid >> 5, lane = tid & 31;
    int wm = (wid & 1) * 64, wn = (wid >> 1) * 32;
    int g = lane >> 2, t4 = lane & 3;

    int lrow = tid >> 1, lkc = (tid & 1) * 8;
    uint4 rah, ral, rbh, rbl;
    auto fetch = [&](int k0) {
        ll ao = (ll)(m0 + lrow) * lda + k0 + lkc;
        rah = *reinterpret_cast<const uint4*>(Ah + ao);
        ral = *reinterpret_cast<const uint4*>(Al + ao);
        int gn = n0 + lrow;
        if (gn < N) {
            ll bo = (ll)gn * ldb + k0 + lkc;
            rbh = *reinterpret_cast<const uint4*>(Bh + bo);
            rbl = *reinterpret_cast<const uint4*>(Bl + bo);
        } else {
            rbh = make_uint4(0, 0, 0, 0); rbl = rbh;
        }
    };
    auto store = [&](int buf) {
        int so = lrow * SPITCH + lkc;
        *reinterpret_cast<uint4*>(&sA[buf][0][so]) = rah;
        *reinterpret_cast<uint4*>(&sA[buf][1][so]) = ral;
        *reinterpret_cast<uint4*>(&sB[buf][0][so]) = rbh;
        *reinterpret_cast<uint4*>(&sB[buf][1][so]) = rbl;
    };

    int mat = lane >> 3, mr = lane & 7;
    int aRow = (mat & 1) * 8 + mr, aCol = (mat >> 1) * 8;
    int bRow = (mat >> 1) * 8 + mr, bCol = (mat & 1) * 8;
    uint32_t aBase = (uint32_t)__cvta_generic_to_shared(&sA[0][0][0]);
    uint32_t bBase = (uint32_t)__cvta_generic_to_shared(&sB[0][0][0]);

    float acc[4][4][4];
    #pragma unroll
    for (int i = 0; i < 4; i++)
        #pragma unroll
        for (int j = 0; j < 4; j++)
            #pragma unroll
            for (int p = 0; p < 4; p++) acc[i][j][p] = 0.f;

    int nk = K >> 4;
    fetch(0); store(0); __syncthreads();

    for (int kt = 0; kt < nk; kt++) {
        int cur = kt & 1;
        if (kt + 1 < nk) fetch((kt + 1) << 4);

        uint32_t ah[4][4], al[4][4], bh[8], bl[8];
        #pragma unroll
        for (int mi = 0; mi < 4; mi++) {
            uint32_t rowoff = (uint32_t)((wm + mi * 16 + aRow) * SPITCH + aCol) * 2;
            ldsm4(ah[mi][0], ah[mi][1], ah[mi][2], ah[mi][3],
                  aBase + (uint32_t)(cur * 2 + 0) * (128 * SPITCH * 2) + rowoff);
            ldsm4(al[mi][0], al[mi][1], al[mi][2], al[mi][3],
                  aBase + (uint32_t)(cur * 2 + 1) * (128 * SPITCH * 2) + rowoff);
        }
        #pragma unroll
        for (int bi = 0; bi < 2; bi++) {
            uint32_t rowoff = (uint32_t)((wn + bi * 16 + bRow) * SPITCH + bCol) * 2;
            ldsm4(bh[bi * 4 + 0], bh[bi * 4 + 1], bh[bi * 4 + 2], bh[bi * 4 + 3],
                  bBase + (uint32_t)(cur * 2 + 0) * (128 * SPITCH * 2) + rowoff);
            ldsm4(bl[bi * 4 + 0], bl[bi * 4 + 1], bl[bi * 4 + 2], bl[bi * 4 + 3],
                  bBase + (uint32_t)(cur * 2 + 1) * (128 * SPITCH * 2) + rowoff);
        }
        #pragma unroll
        for (int mi = 0; mi < 4; mi++)
            #pragma unroll
            for (int ni = 0; ni < 4; ni++) {
                mma16816(acc[mi][ni], ah[mi], &bh[ni * 2]);
                mma16816(acc[mi][ni], ah[mi], &bl[ni * 2]);
                mma16816(acc[mi][ni], al[mi], &bh[ni * 2]);
                mma16816(acc[mi][ni], al[mi], &bl[ni * 2]);
            }
        if (kt + 1 < nk) { store(cur ^ 1); __syncthreads(); }
    }

    #pragma unroll
    for (int mi = 0; mi < 4; mi++) {
        int r0 = m0 + wm + mi * 16 + g;
        #pragma unroll
        for (int ni = 0; ni < 4; ni++) {
            int col = n0 + wn + ni * 8 + t4 * 2;
            if (col >= N) continue;
            ll o0 = (ll)r0 * ldc + col;
            ll o1 = (ll)(r0 + 8) * ldc + col;
            *reinterpret_cast<float2*>(&C[o0]) =
                make_float2(alpha * acc[mi][ni][0], alpha * acc[mi][ni][1]);
            *reinterpret_cast<float2*>(&C[o1]) =
                make_float2(alpha * acc[mi][ni][2], alpha * acc[mi][ni][3]);
        }
    }
}

// 2-way split conversion
__global__ void conv_k(const float* __restrict__ x, bf16* __restrict__ hi,
                       bf16* __restrict__ lo, ll n)
{
    ll stride = (ll)gridDim.x * blockDim.x;
    for (ll i = blockIdx.x * (ll)blockDim.x + threadIdx.x; i < n; i += stride) {
        float v = x[i];
        bf16 h = __float2bfloat16(v);
        hi[i] = h;
        lo[i] = __float2bfloat16(v - __bfloat162float(h));
    }
}

// transpose-convert 2-way: src R x C (ld=lds) -> dst C x R (ld=ldd)
__global__ void convT_k(const float* __restrict__ src, bf16* __restrict__ hi,
                        bf16* __restrict__ lo, int R, int C,
                        int lds, int ldd, int inner,
                        ll sSo, ll sDo, ll sSi, ll sDi)
{
    __shared__ float tile[32][33];
    int z = blockIdx.z, zo = z / inner, zi = z % inner;
    src += zo * sSo + zi * sSi;
    ll doff = zo * sDo + zi * sDi;
    hi += doff; lo += doff;
    int c0 = blockIdx.x * 32, r0 = blockIdx.y * 32;
    int tx = threadIdx.x, ty = threadIdx.y;   // 32 x 8
    #pragma unroll
    for (int i = 0; i < 32; i += 8) {
        int r = r0 + ty + i, c = c0 + tx;
        tile[ty + i][tx] = (r < R && c < C) ? src[(ll)r * lds + c] : 0.f;
    }
    __syncthreads();
    #pragma unroll
    for (int i = 0; i < 32; i += 8) {
        int c = c0 + ty + i, r = r0 + tx;
        if (c < C && r < R) {
            float v = tile[tx][ty + i];
            bf16 h = __float2bfloat16(v);
            hi[(ll)c * ldd + r] = h;
            lo[(ll)c * ldd + r] = __float2bfloat16(v - __bfloat162float(h));
        }
    }
}

// ---------------- fp32 SGEMM (R8/R13, proven) ----------------
template<bool TB, bool ACC>
__global__ void __launch_bounds__(256)
sgemm_k(const float* __restrict__ A, const float* __restrict__ B,
        float* __restrict__ C, int M, int N, int K,
        int lda, int ldb, int ldc, int inner,
        ll sAo, ll sBo, ll sCo, ll sAi, ll sBi, ll sCi, float alpha)
{
    __shared__ float As[2][16][128];
    __shared__ float Bs[2][16][128];
    int z = blockIdx.z, zo = z / inner, zi = z % inner;
    A += zo * sAo + zi * sAi;
    B += zo * sBo + zi * sBi;
    C += zo * sCo + zi * sCi;
    int m0 = blockIdx.y * 128, n0 = blockIdx.x * 128;
    int tid = threadIdx.x;
    int tx = tid & 15, ty = tid >> 4;
    const int arow = tid & 127;
    const int ac4  = tid >> 7;
    float4 pa[2], pb[2];
    auto fetchA = [&](int k0) {
        const float* base = A + (ll)(m0 + arow) * lda + k0;
        pa[0] = *reinterpret_cast<const float4*>(base + ac4 * 4);
        pa[1] = *reinterpret_cast<const float4*>(base + (ac4 + 2) * 4);
    };
    auto storeA = [&](int buf) {
        #pragma unroll
        for (int i = 0; i < 2; i++) {
            int c = (ac4 + i * 2) * 4;
            As[buf][c + 0][arow] = (i ? pa[1].x : pa[0].x);
            As[buf][c + 1][arow] = (i ? pa[1].y : pa[0].y);
            As[buf][c + 2][arow] = (i ? pa[1].z : pa[0].z);
            As[buf][c + 3][arow] = (i ? pa[1].w : pa[0].w);
        }
    };
    auto fetchB = [&](int k0) {
        if (!TB) {
            bool ok = (n0 + (tid & 31) * 4) < N;
            #pragma unroll
            for (int i = 0; i < 2; i++) {
                pb[i] = ok ? *reinterpret_cast<const float4*>(
                                 B + (ll)(k0 + (tid >> 5) + i * 8) * ldb + n0 + (tid & 31) * 4)
                           : make_float4(0.f, 0.f, 0.f, 0.f);
            }
        } else {
            int gn = n0 + arow;
            bool ok = gn < N;
            const float* base = B + (ll)gn * ldb + k0;
            pb[0] = ok ? *reinterpret_cast<const float4*>(base + ac4 * 4)
                       : make_float4(0.f, 0.f, 0.f, 0.f);
            pb[1] = ok ? *reinterpret_cast<const float4*>(base + (ac4 + 2) * 4)
                       : make_float4(0.f, 0.f, 0.f, 0.f);
        }
    };
    auto storeB = [&](int buf) {
        if (!TB) {
            #pragma unroll
            for (int i = 0; i < 2; i++)
                *reinterpret_cast<float4*>(&Bs[buf][(tid >> 5) + i * 8][(tid & 31) * 4]) = pb[i];
        } else {
            #pragma unroll
            for (int i = 0; i < 2; i++) {
                int c = (ac4 + i * 2) * 4;
                Bs[buf][c + 0][arow] = (i ? pb[1].x : pb[0].x);
                Bs[buf][c + 1][arow] = (i ? pb[1].y : pb[0].y);
                Bs[buf][c + 2][arow] = (i ? pb[1].z : pb[0].z);
                Bs[buf][c + 3][arow] = (i ? pb[1].w : pb[0].w);
            }
        }
    };
    float acc[8][8];
    #pragma unroll
    for (int i = 0; i < 8; i++)
        #pragma unroll
        for (int j = 0; j < 8; j++) acc[i][j] = 0.f;
    int nk = K >> 4;
    fetchA(0); fetchB(0);
    storeA(0); storeB(0);
    __syncthreads();
    for (int kt = 0; kt < nk; kt++) {
        int cur = kt & 1;
        if (kt + 1 < nk) { fetchA((kt + 1) << 4); fetchB((kt + 1) << 4); }
        #pragma unroll
        for (int k = 0; k < 16; k++) {
            float4 a0 = *reinterpret_cast<const float4*>(&As[cur][k][ty * 8]);
            float4 a1 = *reinterpret_cast<const float4*>(&As[cur][k][ty * 8 + 4]);
            float4 b0 = *reinterpret_cast<const float4*>(&Bs[cur][k][tx * 8]);
            float4 b1 = *reinterpret_cast<const float4*>(&Bs[cur][k][tx * 8 + 4]);
            float av[8] = {a0.x, a0.y, a0.z, a0.w, a1.x, a1.y, a1.z, a1.w};
            float bv[8] = {b0.x, b0.y, b0.z, b0.w, b1.x, b1.y, b1.z, b1.w};
            #pragma unroll
            for (int i = 0; i < 8; i++)
                #pragma unroll
                for (int j = 0; j < 8; j++)
                    acc[i][j] += av[i] * bv[j];
        }
        if (kt + 1 < nk) {
            storeA(cur ^ 1); storeB(cur ^ 1);
            __syncthreads();
        }
    }
    #pragma unroll
    for (int i = 0; i < 8; i++) {
        int gm = m0 + ty * 8 + i;
        #pragma unroll
        for (int j = 0; j < 8; j++) {
            int gn = n0 + tx * 8 + j;
            if (gn >= N) continue;
            ll off = (ll)gm * ldc + gn;
            float v = alpha * acc[i][j];
            if (ACC) C[off] += v; else C[off] = v;
        }
    }
}

// ---------------- small kernels (identical to R13) ----------------
__global__ void rope_tab_k(float* __restrict__ cs, float* __restrict__ sn)
{
    int t = blockIdx.x, i = threadIdx.x;
    int j = i & 31;
    float ex = (float)(2 * j) / 64.0f;
    float inv = (float)(1.0 / pow(10000.0, (double)ex));
    float ang = (float)t * inv;
    cs[t * HD_ + i] = cosf(ang);
    sn[t * HD_ + i] = sinf(ang);
}

__global__ void prefix_k(const float* __restrict__ cs, const float* __restrict__ sn,
                         double* __restrict__ pc, double* __restrict__ ps)
{
    int d = threadIdx.x;
    double a = 0.0, b = 0.0;
    pc[d] = 0.0; ps[d] = 0.0;
    for (int t = 0; t < T_; t++) {
        a += (double)cs[t * HD_ + d];
        b += (double)sn[t * HD_ + d];
        pc[(t + 1) * HD_ + d] = a;
        ps[(t + 1) * HD_ + d] = b;
    }
}

__global__ void embed_k(const int* __restrict__ ids, const float* __restrict__ em,
                        float* __restrict__ h)
{
    int t = blockIdx.x;
    ll r = ids[t];
    const float* src = em + r * D_;
    float* dst = h + (size_t)t * D_;
    for (int d = threadIdx.x; d < D_; d += 256) dst[d] = src[d];
}

__global__ void rmsnorm_b_k(const float* __restrict__ x, const float* __restrict__ ln,
                            float* __restrict__ y, int rowsPerE,
                            ll sxE, int slnE, ll syE)
{
    int row = blockIdx.x;
    int e = row / rowsPerE, r = row % rowsPerE;
    const float* xr = x + e * sxE + (size_t)r * D_;
    const float* lr = ln + e * slnE;
    float* yr = y + e * syE + (size_t)r * D_;
    __shared__ float red[256];
    float s = 0.f;
    for (int d = threadIdx.x; d < D_; d += 256) { float v = xr[d]; s += v * v; }
    red[threadIdx.x] = s; __syncthreads();
    for (int st = 128; st > 0; st >>= 1) {
        if (threadIdx.x < st) red[threadIdx.x] += red[threadIdx.x + st];
        __syncthreads();
    }
    float rr = rsqrtf(red[0] / (float)D_ + 1e-6f);
    for (int d = threadIdx.x; d < D_; d += 256) yr[d] = xr[d] * rr * lr[d];
}

__global__ void rope_b_k(float* __restrict__ q, float* __restrict__ k,
                         const float* __restrict__ cs, const float* __restrict__ sn,
                         int rowsPerE, int exStride)
{
    int row = blockIdx.x;
    int csRow = (row / rowsPerE) * exStride + (row % rowsPerE);
    int tid = threadIdx.x;
    int h = tid >> 5, i = tid & 31;
    float c1 = cs[csRow * HD_ + i],      s1 = sn[csRow * HD_ + i];
    float c2 = cs[csRow * HD_ + i + 32], s2 = sn[csRow * HD_ + i + 32];
    ll base = (ll)row * D_ + h * HD_ + i;
    float q0 = q[base], q1 = q[base + 32];
    q[base]      = q0 * c1 - q1 * s1;
    q[base + 32] = q1 * c2 + q0 * s2;
    float k0 = k[base], k1 = k[base + 32];
    k[base]      = k0 * c1 - k1 * s1;
    k[base + 32] = k1 * c2 + k0 * s2;
}

__global__ void softmax_causal_k(float* __restrict__ sc, int S)
{
    int i = blockIdx.x, b = blockIdx.y;
    float* row = sc + ((size_t)b * S + i) * (size_t)S;
    int valid = i + 1;
    __shared__ float red[256];
    int tid = threadIdx.x;
    float m = -1e30f;
    for (int j = tid; j < valid; j += 256) m = fmaxf(m, row[j]);
    red[tid] = m; __syncthreads();
    for (int st = 128; st > 0; st >>= 1) {
        if (tid < st) red[tid] = fmaxf(red[tid], red[tid + st]);
        __syncthreads();
    }
    m = red[0]; __syncthreads();
    float sum = 0.f;
    for (int j = tid; j < valid; j += 256) { float e = expf(row[j] - m); row[j] = e; sum += e; }
    red[tid] = sum; __syncthreads();
    for (int st = 128; st > 0; st >>= 1) {
        if (tid < st) red[tid] += red[tid + st];
        __syncthreads();
    }
    float inv = 1.0f / red[0];
    for (int j = tid; j < valid; j += 256) row[j] *= inv;
    for (int j = valid + tid; j < S; j += 256) row[j] = 0.f;
}

__global__ void gelu_k(float* __restrict__ x, ll n)
{
    for (ll i = blockIdx.x * (ll)blockDim.x + threadIdx.x; i < n;
         i += (ll)gridDim.x * blockDim.x) {
        float v = x[i];
        float t = tanhf(0.7978845608028654f * (v + 0.044715f * v * v * v));
        x[i] = 0.5f * v * (1.f + t);
    }
}

__global__ void top2_k(const float* __restrict__ lg, int* __restrict__ sel,
                       float* __restrict__ rho)
{
    int t = blockIdx.x * blockDim.x + threadIdx.x;
    if (t >= T_) return;
    const float* l = lg + (size_t)t * 9;
    int e0 = 0; float b0 = l[0];
    for (int e = 1; e < 9; e++) if (l[e] > b0) { b0 = l[e]; e0 = e; }
    int e1 = -1; float b1 = -1e30f;
    for (int e = 0; e < 9; e++) { if (e == e0) continue; if (l[e] > b1) { b1 = l[e]; e1 = e; } }
    sel[2 * t] = e0; sel[2 * t + 1] = e1;
    rho[t] = 0.5f * (float)((e0 < 8 ? 1 : 0) + (e1 < 8 ? 1 : 0));
}

__global__ void clear_k(int* __restrict__ p, int n)
{
    int i = blockIdx.x * blockDim.x + threadIdx.x;
    if (i < n) p[i] = -1;
}

__global__ void scan_k(const int* __restrict__ sel, int* __restrict__ stok,
                       int* __restrict__ tslot, int* __restrict__ ecnt,
                       int* __restrict__ eov)
{
    int e = threadIdx.x;
    if (e >= 9) return;
    int cnt = 0, ov = T_;
    for (int t = 0; t < T_; t++) {
        #pragma unroll
        for (int j = 0; j < 2; j++) {
            if (sel[2 * t + j] == e) {
                int r = cnt++;
                if (r < CAP_) { stok[e * CAP_ + r] = t; tslot[2 * t + j] = r; }
                else          { tslot[2 * t + j] = -1; if (r == CAP_) ov = t; }
            }
        }
    }
    ecnt[e] = cnt;
    eov[e] = ov;
}

__global__ void gather_k(const float* __restrict__ h, const int* __restrict__ stok,
                         float* __restrict__ xin)
{
    int row = blockIdx.x;
    int tok = stok[row];
    float* xo = xin + (size_t)row * D_;
    if (tok >= 0) {
        const float* hr = h + (size_t)tok * D_;
        for (int d = threadIdx.x; d < D_; d += 256) xo[d] = 0.5f * hr[d];
    } else {
        for (int d = threadIdx.x; d < D_; d += 256) xo[d] = 0.f;
    }
}

__global__ void fill_cossin_k(const int* __restrict__ stok, const int* __restrict__ ecnt,
                              const int* __restrict__ eov,
                              const double* __restrict__ pc, const double* __restrict__ ps,
                              float* __restrict__ csr, float* __restrict__ snr)
{
    int row = blockIdx.x;
    int e = row / CAP_, c = row % CAP_;
    int d = threadIdx.x;
    int m = ecnt[e];
    int mc = m < CAP_ ? m : CAP_;
    bool active = (c < mc) || (m == 0 && c == 0);
    if (!active) {
        csr[row * HD_ + d] = 0.f;
        snr[row * HD_ + d] = 0.f;
        return;
    }
    int start = (c == 0) ? 0 : stok[e * CAP_ + c];
    int end;
    if (m == 0)            end = T_;
    else if (c + 1 < m)    end = (c + 1 < CAP_) ? stok[e * CAP_ + c + 1] : eov[e];
    else                   end = T_;
    csr[row * HD_ + d] = (float)(pc[end * HD_ + d] - pc[start * HD_ + d]);
    snr[row * HD_ + d] = (float)(ps[end * HD_ + d] - ps[start * HD_ + d]);
}

__global__ void scale_k(float* __restrict__ h, const float* __restrict__ rho)
{
    int t = blockIdx.x;
    float f = 1.0f - rho[t];
    float* hr = h + (size_t)t * D_;
    for (int d = threadIdx.x; d < D_; d += 256) hr[d] *= f;
}

__global__ void combine_k(float* __restrict__ h, const float* __restrict__ eout,
                          const int* __restrict__ sel, const int* __restrict__ tslot)
{
    int t = blockIdx.x;
    float* hr = h + (size_t)t * D_;
    #pragma unroll
    for (int j = 0; j < 2; j++) {
        int e = sel[2 * t + j];
        int s = tslot[2 * t + j];
        if (e < 8 && s >= 0) {
            const float* src = eout + ((size_t)e * CAP_ + s) * D_;
            for (int d = threadIdx.x; d < D_; d += 256) hr[d] += 0.5f * src[d];
        }
    }
}

// ---------------- host helpers ----------------
static bf16 *BH = nullptr, *BL = nullptr;

static void gemm(bool tb, bool acc, const float* A, const float* B, float* C,
                 int M, int N, int K, int lda, int ldb, int ldc,
                 int nz, int inner,
                 ll sAo, ll sBo, ll sCo, ll sAi, ll sBi, ll sCi, float alpha)
{
    dim3 g((N + 127) / 128, M / 128, nz), b(256);
    if (!tb && !acc)      sgemm_k<false,false><<<g,b>>>(A,B,C,M,N,K,lda,ldb,ldc,inner,sAo,sBo,sCo,sAi,sBi,sCi,alpha);
    else if (!tb && acc)  sgemm_k<false,true ><<<g,b>>>(A,B,C,M,N,K,lda,ldb,ldc,inner,sAo,sBo,sCo,sAi,sBi,sCi,alpha);
    else if (tb && !acc)  sgemm_k<true ,false><<<g,b>>>(A,B,C,M,N,K,lda,ldb,ldc,inner,sAo,sBo,sCo,sAi,sBi,sCi,alpha);
    else                  sgemm_k<true ,true ><<<g,b>>>(A,B,C,M,N,K,lda,ldb,ldc,inner,sAo,sBo,sCo,sAi,sBi,sCi,alpha);
}

static void tgemmb(ll aOff, ll bOff, float* C,
                   int M, int N, int K, int lda, int ldb, int ldc,
                   int nz, int inner,
                   ll sAo, ll sBo, ll sCo, ll sAi, ll sBi, ll sCi, float alpha)
{
    dim3 g((N + 127) / 128, M / 128, nz), b(256);
    tgemm_b_k<<<g, b>>>(BH + aOff, BL + aOff, BH + bOff, BL + bOff, C,
                        M, N, K, lda, ldb, ldc, inner,
                        sAo, sBo, sCo, sAi, sBi, sCi, alpha);
}

static void conv(const float* x, ll bOff, ll n)
{
    int blocks = (int)((n + 255) / 256);
    if (blocks > 4096) blocks = 4096;
    conv_k<<<blocks, 256>>>(x, BH + bOff, BL + bOff, n);
}

static void convT(const float* src, ll bOff, int R, int C, int lds, int ldd,
                  int nz, int inner, ll sSo, ll sDo, ll sSi, ll sDi)
{
    dim3 g((C + 31) / 32, (R + 31) / 32, nz), b(32, 8);
    convT_k<<<g, b>>>(src, BH + bOff, BL + bOff, R, C, lds, ldd, inner,
                      sSo, sDo, sSi, sDi);
}

// ---------------- entry point ----------------
extern "C" void kernel_launch(void* const* d_in, const int* in_sizes, int n_in,
                              void* d_out, int out_size)
{
    (void)in_sizes; (void)n_in; (void)out_size;
    const int*   ids     = (const int*)  d_in[0];
    const float* embed   = (const float*)d_in[1];
    const float* routerW = (const float*)d_in[2];
    const float* b_aln   = (const float*)d_in[3];
    const float* b_wq    = (const float*)d_in[4];
    const float* b_wk    = (const float*)d_in[5];
    const float* b_wv    = (const float*)d_in[6];
    const float* b_wo    = (const float*)d_in[7];
    const float* b_fln   = (const float*)d_in[8];
    const float* b_w1    = (const float*)d_in[9];
    const float* b_w2    = (const float*)d_in[10];
    const float* a_ln    = (const float*)d_in[11];
    const float* a_wq    = (const float*)d_in[12];
    const float* a_wk    = (const float*)d_in[13];
    const float* a_wv    = (const float*)d_in[14];
    const float* a_wo    = (const float*)d_in[15];
    const float* f_ln    = (const float*)d_in[16];
    const float* f_w1    = (const float*)d_in[17];
    const float* f_w2    = (const float*)d_in[18];
    const float* ln_out  = (const float*)d_in[19];
    float* out = (float*)d_out;

    float* W = nullptr; int* WI = nullptr; double* WD = nullptr;
    cudaGetSymbolAddress((void**)&W,  g_ws);
    cudaGetSymbolAddress((void**)&WI, g_wsi);
    cudaGetSymbolAddress((void**)&WD, g_wsd);
    cudaGetSymbolAddress((void**)&BH, g_bh);
    cudaGetSymbolAddress((void**)&BL, g_bl);

    float *Hh  = W + OFF_H,   *XN  = W + OFF_XN,  *Q   = W + OFF_Q,
          *Kb  = W + OFF_K,   *Vb  = W + OFF_V,   *AO  = W + OFF_AO,
          *FF  = W + OFF_FFN, *SC  = W + OFF_SC,  *XIN = W + OFF_XIN,
          *EOUT= W + OFF_EOUT,*CS  = W + OFF_COS, *SN  = W + OFF_SIN,
          *CSR = W + OFF_COSR,*SNR = W + OFF_SINR,*LG  = W + OFF_LG,
          *RHO = W + OFF_RHO;
    double *PC = WD + OFF_PC, *PS = WD + OFF_PS;
    int *SEL = WI + IOFF_SEL, *STOK = WI + IOFF_STOK, *TSLOT = WI + IOFF_TSLOT,
        *ECNT = WI + IOFF_ECNT, *EOV = WI + IOFF_EOV;

    const ll CD  = (ll)CAP_ * D_;
    const ll DD  = (ll)D_ * D_;
    const ll CC  = (ll)CAP_ * CAP_;
    const ll CF  = (ll)CAP_ * DFF_;
    const ll DF  = (ll)D_ * DFF_;

    // one-time bf16 conversions: embed + hop-4 expert weights (transposed n x k)
    conv(embed, BO_EMB, VDc);
    convT(a_wq, BO_AWQ, D_, D_, D_, D_, 4, 1, DD, DD, 0, 0);
    convT(a_wk, BO_AWK, D_, D_, D_, D_, 4, 1, DD, DD, 0, 0);
    convT(a_wv, BO_AWV, D_, D_, D_, D_, 4, 1, DD, DD, 0, 0);
    convT(a_wo, BO_AWO, D_, D_, D_, D_, 4, 1, DD, DD, 0, 0);
    convT(f_w1, BO_FW1, D_, DFF_, DFF_, D_, 4, 1, DF, DF, 0, 0);
    convT(f_w2, BO_FW2, DFF_, D_, D_, DFF_, 4, 1, DF, DF, 0, 0);

    // rope tables + prefix sums + embedding
    rope_tab_k<<<T_, HD_>>>(CS, SN);
    prefix_k<<<1, HD_>>>(CS, SN, PC, PS);
    embed_k<<<T_, 256>>>(ids, embed, Hh);

    // ---------------- backbone attention (fp32) ----------------
    rmsnorm_b_k<<<T_, 256>>>(Hh, b_aln, XN, T_, 0, 0, 0);
    gemm(false,false, XN, b_wq, Q,  T_, D_, D_, D_, D_, D_, 1,1, 0,0,0, 0,0,0, 1.f);
    gemm(false,false, XN, b_wk, Kb, T_, D_, D_, D_, D_, D_, 1,1, 0,0,0, 0,0,0, 1.f);
    gemm(false,false, XN, b_wv, Vb, T_, D_, D_, D_, D_, D_, 1,1, 0,0,0, 0,0,0, 1.f);
    rope_b_k<<<T_, H_ * 32>>>(Q, Kb, CS, SN, T_, 0);
    gemm(true, false, Q, Kb, SC, T_, T_, HD_, D_, D_, T_,
         H_, H_, 0,0,0, HD_, HD_, (ll)T_ * T_, 0.125f);
    softmax_causal_k<<<dim3(T_, H_), 256>>>(SC, T_);
    gemm(false,false, SC, Vb, AO, T_, HD_, T_, T_, D_, D_,
         H_, H_, 0,0,0, (ll)T_ * T_, HD_, HD_, 1.f);
    gemm(false,true, AO, b_wo, Hh, T_, D_, D_, D_, D_, D_, 1,1, 0,0,0, 0,0,0, 1.f);

    // ---------------- backbone FFN (fp32) ----------------
    rmsnorm_b_k<<<T_, 256>>>(Hh, b_fln, XN, T_, 0, 0, 0);
    gemm(false,false, XN, b_w1, FF, T_, DFF_, D_, D_, DFF_, DFF_, 1,1, 0,0,0, 0,0,0, 1.f);
    gelu_k<<<2048, 256>>>(FF, (ll)T_ * DFF_);
    gemm(false,true, FF, b_w2, Hh, T_, D_, DFF_, DFF_, D_, D_, 1,1, 0,0,0, 0,0,0, 1.f);

    for (int r = 0; r < NHOPS_; r++) {
        gemm(true, false, Hh, routerW + (size_t)r * 9 * D_, LG,
             T_, 9, D_, D_, D_, 9, 1,1, 0,0,0, 0,0,0, 1.f);
        top2_k<<<(T_ + 255) / 256, 256>>>(LG, SEL, RHO);
        clear_k<<<(9 * CAP_ + 255) / 256, 256>>>(STOK, 9 * CAP_);
        scan_k<<<1, 32>>>(SEL, STOK, TSLOT, ECNT, EOV);
        gather_k<<<8 * CAP_, 256>>>(Hh, STOK, XIN);
        fill_cossin_k<<<8 * CAP_, HD_>>>(STOK, ECNT, EOV, PC, PS, CSR, SNR);

        if (r < NHOPS_ - 1) {
            // ===== hops 1-3: fp32 expert phase (routing-sensitive) =====
            rmsnorm_b_k<<<4 * CAP_, 256>>>(XIN, a_ln, XN, CAP_, 2 * CD, D_, CD);
            gemm(false,false, XN, a_wq, Q,  CAP_, D_, D_, D_, D_, D_,
                 4,1, CD, DD, CD, 0,0,0, 1.f);
            gemm(false,false, XN, a_wk, Kb, CAP_, D_, D_, D_, D_, D_,
                 4,1, CD, DD, CD, 0,0,0, 1.f);
            gemm(false,false, XN, a_wv, Vb, CAP_, D_, D_, D_, D_, D_,
                 4,1, CD, DD, CD, 0,0,0, 1.f);
            rope_b_k<<<4 * CAP_, H_ * 32>>>(Q, Kb, CSR, SNR, CAP_, 2 * CAP_);
            gemm(true, false, Q, Kb, SC, CAP_, CAP_, HD_, D_, D_, CAP_,
                 4 * H_, H_, CD, CD, 16 * CC, HD_, HD_, CC, 0.125f);
            softmax_causal_k<<<dim3(CAP_, 4 * H_), 256>>>(SC, CAP_);
            gemm(false,false, SC, Vb, AO, CAP_, HD_, CAP_, CAP_, D_, D_,
                 4 * H_, H_, 16 * CC, CD, CD, CC, HD_, HD_, 1.f);
            gemm(false,false, AO, a_wo, EOUT, CAP_, D_, D_, D_, D_, D_,
                 4,1, CD, DD, CD, 0,0,0, 1.f);

            rmsnorm_b_k<<<4 * CAP_, 256>>>(XIN + CD, f_ln, XN, CAP_, 2 * CD, D_, CD);
            gemm(false,false, XN, f_w1, FF, CAP_, DFF_, D_, D_, DFF_, DFF_,
                 4,1, CD, DF, CF, 0,0,0, 1.f);
            gelu_k<<<2048, 256>>>(FF, (ll)4 * CAP_ * DFF_);
            gemm(false,false, FF, f_w2, EOUT + 4 * CD, CAP_, D_, DFF_, DFF_, D_, D_,
                 4,1, CF, DF, CD, 0,0,0, 1.f);
        } else {
            // ===== hop 4: bf16 tensor expert phase (no downstream router) =====
            // attention experts
            rmsnorm_b_k<<<4 * CAP_, 256>>>(XIN, a_ln, XN, CAP_, 2 * CD, D_, CD);
            conv(XN, BO_XN, TDc);
            tgemmb(BO_XN, BO_AWQ, Q,  CAP_, D_, D_, D_, D_, D_,
                   4,1, CD, DD, CD, 0,0,0, 1.f);
            tgemmb(BO_XN, BO_AWK, Kb, CAP_, D_, D_, D_, D_, D_,
                   4,1, CD, DD, CD, 0,0,0, 1.f);
            tgemmb(BO_XN, BO_AWV, Vb, CAP_, D_, D_, D_, D_, D_,
                   4,1, CD, DD, CD, 0,0,0, 1.f);
            rope_b_k<<<4 * CAP_, H_ * 32>>>(Q, Kb, CSR, SNR, CAP_, 2 * CAP_);
            conv(Q, BO_Q, 2 * TDc);                     // Q,K contiguous both spaces
            convT(Vb, BO_VT, CAP_, HD_, D_, CAP_, 4 * H_, H_,
                  CD, CD, HD_, (ll)HD_ * CAP_);
            tgemmb(BO_Q, BO_K, SC, CAP_, CAP_, HD_, D_, D_, CAP_,
                   4 * H_, H_, CD, CD, 16 * CC, HD_, HD_, CC, 0.125f);
            softmax_causal_k<<<dim3(CAP_, 4 * H_), 256>>>(SC, CAP_);
            conv(SC, BO_SC, (ll)4 * H_ * CC);
            tgemmb(BO_SC, BO_VT, AO, CAP_, HD_, CAP_, CAP_, CAP_, D_,
                   4 * H_, H_, 16 * CC, CD, CD, CC, (ll)HD_ * CAP_, HD_, 1.f);
            conv(AO, BO_AO, TDc);
            tgemmb(BO_AO, BO_AWO, EOUT, CAP_, D_, D_, D_, D_, D_,
                   4,1, CD, DD, CD, 0,0,0, 1.f);

            // FFN experts
            rmsnorm_b_k<<<4 * CAP_, 256>>>(XIN + CD, f_ln, XN, CAP_, 2 * CD, D_, CD);
            conv(XN, BO_XN, TDc);
            tgemmb(BO_XN, BO_FW1, FF, CAP_, DFF_, D_, D_, D_, DFF_,
                   4,1, CD, DF, CF, 0,0,0, 1.f);
            gelu_k<<<2048, 256>>>(FF, (ll)4 * CAP_ * DFF_);
            conv(FF, BO_FF, (ll)4 * CF);
            tgemmb(BO_FF, BO_FW2, EOUT + 4 * CD, CAP_, D_, DFF_, DFF_, DFF_, D_,
                   4,1, CF, DF, CD, 0,0,0, 1.f);
        }

        scale_k<<<T_, 256>>>(Hh, RHO);
        combine_k<<<T_, 256>>>(Hh, EOUT, SEL, TSLOT);
    }

    // final: rms(h)*ln_out @ embed^T — bf16 2-way 4-term tensor GEMM (R13-proven)
    rmsnorm_b_k<<<T_, 256>>>(Hh, ln_out, XN, T_, 0, 0, 0);
    conv_k<<<2048, 256>>>(XN, BH + BO_XNO, BL + BO_XNO, TDc);
    {
        dim3 g(V_ / 128, T_ / 128, 1), b(256);
        tgemm_k<<<g, b>>>(BH + BO_XNO, BL + BO_XNO, BH + BO_EMB, BL + BO_EMB,
                          out, T_, V_, D_, D_, D_, V_, 1.f);
    }
}

// round 17
// speedup vs baseline: 3.2615x; 1.0267x over previous
#include <cuda_runtime.h>
#include <cuda_bf16.h>
#include <math.h>
#include <stdint.h>

// ---------------- model constants ----------------
#define D_    1024
#define V_    32000
#define DFF_  4096
#define H_    16
#define T_    2048
#define HD_   64
#define CAP_  512
#define NHOPS_ 4

typedef long long ll;
typedef __nv_bfloat16 bf16;

// ---------------- fp32 workspace ----------------
constexpr size_t SZ_TD   = (size_t)T_ * D_;
constexpr size_t OFF_H   = 0;
constexpr size_t OFF_XN  = OFF_H   + SZ_TD;
constexpr size_t OFF_Q   = OFF_XN  + SZ_TD;
constexpr size_t OFF_K   = OFF_Q   + SZ_TD;
constexpr size_t OFF_V   = OFF_K   + SZ_TD;
constexpr size_t OFF_AO  = OFF_V   + SZ_TD;
constexpr size_t OFF_FFN = OFF_AO  + SZ_TD;
constexpr size_t OFF_SC  = OFF_FFN + (size_t)T_ * DFF_;
constexpr size_t OFF_XIN = OFF_SC  + (size_t)H_ * T_ * T_;
constexpr size_t OFF_EOUT= OFF_XIN + (size_t)8 * CAP_ * D_;
constexpr size_t OFF_COS = OFF_EOUT+ (size_t)8 * CAP_ * D_;
constexpr size_t OFF_SIN = OFF_COS + (size_t)T_ * HD_;
constexpr size_t OFF_COSR= OFF_SIN + (size_t)T_ * HD_;
constexpr size_t OFF_SINR= OFF_COSR+ (size_t)8 * CAP_ * HD_;
constexpr size_t OFF_LG  = OFF_SINR+ (size_t)8 * CAP_ * HD_;
constexpr size_t OFF_RHO = OFF_LG  + (size_t)T_ * 9;
constexpr size_t WS_TOTAL= OFF_RHO + (size_t)T_;
__device__ float g_ws[WS_TOTAL];

constexpr size_t OFF_PC = 0;
constexpr size_t OFF_PS = (size_t)(T_ + 1) * HD_;
constexpr size_t WSD_TOTAL = 2 * (size_t)(T_ + 1) * HD_;
__device__ double g_wsd[WSD_TOTAL];

constexpr size_t IOFF_SEL   = 0;
constexpr size_t IOFF_STOK  = IOFF_SEL  + 2 * T_;
constexpr size_t IOFF_TSLOT = IOFF_STOK + 9 * CAP_;
constexpr size_t IOFF_ECNT  = IOFF_TSLOT + 2 * T_;
constexpr size_t IOFF_EOV   = IOFF_ECNT + 9;
constexpr size_t WSI_TOTAL  = IOFF_EOV + 9;
__device__ int g_wsi[WSI_TOTAL];

// ---------------- bf16 hi/lo workspace ----------------
constexpr ll TDc = (ll)T_ * D_;
constexpr ll DDc = (ll)D_ * D_;
constexpr ll DFc = (ll)D_ * DFF_;
constexpr ll VDc = (ll)V_ * D_;
constexpr ll CDc = (ll)CAP_ * D_;
constexpr ll CCc = (ll)CAP_ * CAP_;
constexpr ll CFc = (ll)CAP_ * DFF_;

constexpr ll BO_XN  = 0;
constexpr ll BO_Q   = BO_XN + TDc;
constexpr ll BO_K   = BO_Q  + TDc;          // must stay = BO_Q + TDc (contig conv)
constexpr ll BO_VT  = BO_K  + TDc;
constexpr ll BO_AO  = BO_VT + TDc;
constexpr ll BO_FF  = BO_AO + TDc;
constexpr ll BO_SC  = BO_FF + (ll)4 * CFc;
constexpr ll BO_AWQ = BO_SC + (ll)4 * H_ * CCc;
constexpr ll BO_AWK = BO_AWQ + 4 * DDc;
constexpr ll BO_AWV = BO_AWK + 4 * DDc;
constexpr ll BO_AWO = BO_AWV + 4 * DDc;
constexpr ll BO_FW1 = BO_AWO + 4 * DDc;
constexpr ll BO_FW2 = BO_FW1 + 4 * DFc;
constexpr ll BO_XNO = BO_FW2 + 4 * DFc;
constexpr ll BO_EMB = BO_XNO + TDc;
constexpr ll BT2    = BO_EMB + VDc;
__device__ bf16 g_bh[BT2];
__device__ bf16 g_bl[BT2];

// cmode: 0 = normal; 1 = causal scores (skip tiles fully above diagonal);
//        2 = causal PV (clamp K to m0+128 — drops only exact zeros).

// ================= bf16 2-way 4-term tensor GEMMs (R13/R14-proven) =================
#define SPITCH 24

__device__ __forceinline__ void ldsm4(uint32_t& r0, uint32_t& r1,
                                      uint32_t& r2, uint32_t& r3, uint32_t a)
{
    asm volatile("ldmatrix.sync.aligned.m8n8.x4.shared.b16 {%0,%1,%2,%3}, [%4];"
                 : "=r"(r0), "=r"(r1), "=r"(r2), "=r"(r3) : "r"(a));
}
__device__ __forceinline__ void mma16816(float* c, const uint32_t* a, const uint32_t* b)
{
    asm volatile("mma.sync.aligned.m16n8k16.row.col.f32.bf16.bf16.f32 "
                 "{%0,%1,%2,%3}, {%4,%5,%6,%7}, {%8,%9}, {%0,%1,%2,%3};"
                 : "+f"(c[0]), "+f"(c[1]), "+f"(c[2]), "+f"(c[3])
                 : "r"(a[0]), "r"(a[1]), "r"(a[2]), "r"(a[3]), "r"(b[0]), "r"(b[1]));
}

// ---- non-batched (R13-proven) — vocab GEMM only ----
__global__ void __launch_bounds__(256)
tgemm_k(const bf16* __restrict__ Ah, const bf16* __restrict__ Al,
        const bf16* __restrict__ Bh, const bf16* __restrict__ Bl,
        float* __restrict__ C, int M, int N, int K,
        int lda, int ldb, int ldc, float alpha)
{
    __shared__ bf16 sA[2][2][128 * SPITCH];
    __shared__ bf16 sB[2][2][128 * SPITCH];
    int m0 = blockIdx.y * 128, n0 = blockIdx.x * 128;
    int tid = threadIdx.x, wid = tid >> 5, lane = tid & 31;
    int wm = (wid & 1) * 64, wn = (wid >> 1) * 32;
    int g = lane >> 2, t4 = lane & 3;

    int lrow = tid >> 1, lkc = (tid & 1) * 8;
    uint4 rah, ral, rbh, rbl;
    auto fetch = [&](int k0) {
        ll ao = (ll)(m0 + lrow) * lda + k0 + lkc;
        rah = *reinterpret_cast<const uint4*>(Ah + ao);
        ral = *reinterpret_cast<const uint4*>(Al + ao);
        int gn = n0 + lrow;
        if (gn < N) {
            ll bo = (ll)gn * ldb + k0 + lkc;
            rbh = *reinterpret_cast<const uint4*>(Bh + bo);
            rbl = *reinterpret_cast<const uint4*>(Bl + bo);
        } else {
            rbh = make_uint4(0, 0, 0, 0); rbl = rbh;
        }
    };
    auto store = [&](int buf) {
        int so = lrow * SPITCH + lkc;
        *reinterpret_cast<uint4*>(&sA[buf][0][so]) = rah;
        *reinterpret_cast<uint4*>(&sA[buf][1][so]) = ral;
        *reinterpret_cast<uint4*>(&sB[buf][0][so]) = rbh;
        *reinterpret_cast<uint4*>(&sB[buf][1][so]) = rbl;
    };

    int mat = lane >> 3, mr = lane & 7;
    int aRow = (mat & 1) * 8 + mr, aCol = (mat >> 1) * 8;
    int bRow = (mat >> 1) * 8 + mr, bCol = (mat & 1) * 8;
    uint32_t aBase = (uint32_t)__cvta_generic_to_shared(&sA[0][0][0]);
    uint32_t bBase = (uint32_t)__cvta_generic_to_shared(&sB[0][0][0]);

    float acc[4][4][4];
    #pragma unroll
    for (int i = 0; i < 4; i++)
        #pragma unroll
        for (int j = 0; j < 4; j++)
            #pragma unroll
            for (int p = 0; p < 4; p++) acc[i][j][p] = 0.f;

    int nk = K >> 4;
    fetch(0); store(0); __syncthreads();

    for (int kt = 0; kt < nk; kt++) {
        int cur = kt & 1;
        if (kt + 1 < nk) fetch((kt + 1) << 4);

        uint32_t ah[4][4], al[4][4], bh[8], bl[8];
        #pragma unroll
        for (int mi = 0; mi < 4; mi++) {
            uint32_t rowoff = (uint32_t)((wm + mi * 16 + aRow) * SPITCH + aCol) * 2;
            ldsm4(ah[mi][0], ah[mi][1], ah[mi][2], ah[mi][3],
                  aBase + (uint32_t)(cur * 2 + 0) * (128 * SPITCH * 2) + rowoff);
            ldsm4(al[mi][0], al[mi][1], al[mi][2], al[mi][3],
                  aBase + (uint32_t)(cur * 2 + 1) * (128 * SPITCH * 2) + rowoff);
        }
        #pragma unroll
        for (int bi = 0; bi < 2; bi++) {
            uint32_t rowoff = (uint32_t)((wn + bi * 16 + bRow) * SPITCH + bCol) * 2;
            ldsm4(bh[bi * 4 + 0], bh[bi * 4 + 1], bh[bi * 4 + 2], bh[bi * 4 + 3],
                  bBase + (uint32_t)(cur * 2 + 0) * (128 * SPITCH * 2) + rowoff);
            ldsm4(bl[bi * 4 + 0], bl[bi * 4 + 1], bl[bi * 4 + 2], bl[bi * 4 + 3],
                  bBase + (uint32_t)(cur * 2 + 1) * (128 * SPITCH * 2) + rowoff);
        }
        #pragma unroll
        for (int mi = 0; mi < 4; mi++)
            #pragma unroll
            for (int ni = 0; ni < 4; ni++) {
                mma16816(acc[mi][ni], ah[mi], &bh[ni * 2]);
                mma16816(acc[mi][ni], ah[mi], &bl[ni * 2]);
                mma16816(acc[mi][ni], al[mi], &bh[ni * 2]);
                mma16816(acc[mi][ni], al[mi], &bl[ni * 2]);
            }
        if (kt + 1 < nk) { store(cur ^ 1); __syncthreads(); }
    }

    #pragma unroll
    for (int mi = 0; mi < 4; mi++) {
        int r0 = m0 + wm + mi * 16 + g;
        #pragma unroll
        for (int ni = 0; ni < 4; ni++) {
            int col = n0 + wn + ni * 8 + t4 * 2;
            if (col >= N) continue;
            ll o0 = (ll)r0 * ldc + col;
            ll o1 = (ll)(r0 + 8) * ldc + col;
            *reinterpret_cast<float2*>(&C[o0]) =
                make_float2(alpha * acc[mi][ni][0], alpha * acc[mi][ni][1]);
            *reinterpret_cast<float2*>(&C[o1]) =
                make_float2(alpha * acc[mi][ni][2], alpha * acc[mi][ni][3]);
        }
    }
}

// ---- batched (R14-proven on all expert shapes) + causal modes ----
__global__ void __launch_bounds__(256)
tgemm_b_k(const bf16* __restrict__ Ah, const bf16* __restrict__ Al,
          const bf16* __restrict__ Bh, const bf16* __restrict__ Bl,
          float* __restrict__ C, int M, int N, int K,
          int lda, int ldb, int ldc, int inner,
          ll sAo, ll sBo, ll sCo, ll sAi, ll sBi, ll sCi, float alpha, int cmode)
{
    __shared__ bf16 sA[2][2][128 * SPITCH];
    __shared__ bf16 sB[2][2][128 * SPITCH];
    int m0 = blockIdx.y * 128, n0 = blockIdx.x * 128;
    if (cmode == 1 && n0 >= m0 + 128) return;      // score tile fully above diagonal
    if (cmode == 2) { int ke = m0 + 128; if (ke < K) K = ke; }  // PV: drop exact zeros
    int z = blockIdx.z, zo = z / inner, zi = z % inner;
    ll aoff = zo * sAo + zi * sAi, boff = zo * sBo + zi * sBi;
    Ah += aoff; Al += aoff;
    Bh += boff; Bl += boff;
    C  += zo * sCo + zi * sCi;
    int tid = threadIdx.x, wid = tid >> 5, lane = tid & 31;
    int wm = (wid & 1) * 64, wn = (wid >> 1) * 32;
    int g = lane >> 2, t4 = lane & 3;

    int lrow = tid >> 1, lkc = (tid & 1) * 8;
    uint4 rah, ral, rbh, rbl;
    auto fetch = [&](int k0) {
        ll ao = (ll)(m0 + lrow) * lda + k0 + lkc;
        rah = *reinterpret_cast<const uint4*>(Ah + ao);
        ral = *reinterpret_cast<const uint4*>(Al + ao);
        int gn = n0 + lrow;
        if (gn < N) {
            ll bo = (ll)gn * ldb + k0 + lkc;
            rbh = *reinterpret_cast<const uint4*>(Bh + bo);
            rbl = *reinterpret_cast<const uint4*>(Bl + bo);
        } else {
            rbh = make_uint4(0, 0, 0, 0); rbl = rbh;
        }
    };
    auto store = [&](int buf) {
        int so = lrow * SPITCH + lkc;
        *reinterpret_cast<uint4*>(&sA[buf][0][so]) = rah;
        *reinterpret_cast<uint4*>(&sA[buf][1][so]) = ral;
        *reinterpret_cast<uint4*>(&sB[buf][0][so]) = rbh;
        *reinterpret_cast<uint4*>(&sB[buf][1][so]) = rbl;
    };

    int mat = lane >> 3, mr = lane & 7;
    int aRow = (mat & 1) * 8 + mr, aCol = (mat >> 1) * 8;
    int bRow = (mat >> 1) * 8 + mr, bCol = (mat & 1) * 8;
    uint32_t aBase = (uint32_t)__cvta_generic_to_shared(&sA[0][0][0]);
    uint32_t bBase = (uint32_t)__cvta_generic_to_shared(&sB[0][0][0]);

    float acc[4][4][4];
    #pragma unroll
    for (int i = 0; i < 4; i++)
        #pragma unroll
        for (int j = 0; j < 4; j++)
            #pragma unroll
            for (int p = 0; p < 4; p++) acc[i][j][p] = 0.f;

    int nk = K >> 4;
    fetch(0); store(0); __syncthreads();

    for (int kt = 0; kt < nk; kt++) {
        int cur = kt & 1;
        if (kt + 1 < nk) fetch((kt + 1) << 4);

        uint32_t ah[4][4], al[4][4], bh[8], bl[8];
        #pragma unroll
        for (int mi = 0; mi < 4; mi++) {
            uint32_t rowoff = (uint32_t)((wm + mi * 16 + aRow) * SPITCH + aCol) * 2;
            ldsm4(ah[mi][0], ah[mi][1], ah[mi][2], ah[mi][3],
                  aBase + (uint32_t)(cur * 2 + 0) * (128 * SPITCH * 2) + rowoff);
            ldsm4(al[mi][0], al[mi][1], al[mi][2], al[mi][3],
                  aBase + (uint32_t)(cur * 2 + 1) * (128 * SPITCH * 2) + rowoff);
        }
        #pragma unroll
        for (int bi = 0; bi < 2; bi++) {
            uint32_t rowoff = (uint32_t)((wn + bi * 16 + bRow) * SPITCH + bCol) * 2;
            ldsm4(bh[bi * 4 + 0], bh[bi * 4 + 1], bh[bi * 4 + 2], bh[bi * 4 + 3],
                  bBase + (uint32_t)(cur * 2 + 0) * (128 * SPITCH * 2) + rowoff);
            ldsm4(bl[bi * 4 + 0], bl[bi * 4 + 1], bl[bi * 4 + 2], bl[bi * 4 + 3],
                  bBase + (uint32_t)(cur * 2 + 1) * (128 * SPITCH * 2) + rowoff);
        }
        #pragma unroll
        for (int mi = 0; mi < 4; mi++)
            #pragma unroll
            for (int ni = 0; ni < 4; ni++) {
                mma16816(acc[mi][ni], ah[mi], &bh[ni * 2]);
                mma16816(acc[mi][ni], ah[mi], &bl[ni * 2]);
                mma16816(acc[mi][ni], al[mi], &bh[ni * 2]);
                mma16816(acc[mi][ni], al[mi], &bl[ni * 2]);
            }
        if (kt + 1 < nk) { store(cur ^ 1); __syncthreads(); }
    }

    #pragma unroll
    for (int mi = 0; mi < 4; mi++) {
        int r0 = m0 + wm + mi * 16 + g;
        #pragma unroll
        for (int ni = 0; ni < 4; ni++) {
            int col = n0 + wn + ni * 8 + t4 * 2;
            if (col >= N) continue;
            ll o0 = (ll)r0 * ldc + col;
            ll o1 = (ll)(r0 + 8) * ldc + col;
            *reinterpret_cast<float2*>(&C[o0]) =
                make_float2(alpha * acc[mi][ni][0], alpha * acc[mi][ni][1]);
            *reinterpret_cast<float2*>(&C[o1]) =
                make_float2(alpha * acc[mi][ni][2], alpha * acc[mi][ni][3]);
        }
    }
}

// 2-way bf16 split conversion
__global__ void conv_k(const float* __restrict__ x, bf16* __restrict__ hi,
                       bf16* __restrict__ lo, ll n)
{
    ll stride = (ll)gridDim.x * blockDim.x;
    for (ll i = blockIdx.x * (ll)blockDim.x + threadIdx.x; i < n; i += stride) {
        float v = x[i];
        bf16 h = __float2bfloat16(v);
        hi[i] = h;
        lo[i] = __float2bfloat16(v - __bfloat162float(h));
    }
}

// transpose-convert 2-way bf16: src R x C (ld=lds) -> dst C x R (ld=ldd)
__global__ void convT_k(const float* __restrict__ src, bf16* __restrict__ hi,
                        bf16* __restrict__ lo, int R, int C,
                        int lds, int ldd, int inner,
                        ll sSo, ll sDo, ll sSi, ll sDi)
{
    __shared__ float tile[32][33];
    int z = blockIdx.z, zo = z / inner, zi = z % inner;
    src += zo * sSo + zi * sSi;
    ll doff = zo * sDo + zi * sDi;
    hi += doff; lo += doff;
    int c0 = blockIdx.x * 32, r0 = blockIdx.y * 32;
    int tx = threadIdx.x, ty = threadIdx.y;
    #pragma unroll
    for (int i = 0; i < 32; i += 8) {
        int r = r0 + ty + i, c = c0 + tx;
        tile[ty + i][tx] = (r < R && c < C) ? src[(ll)r * lds + c] : 0.f;
    }
    __syncthreads();
    #pragma unroll
    for (int i = 0; i < 32; i += 8) {
        int c = c0 + ty + i, r = r0 + tx;
        if (c < C && r < R) {
            float v = tile[tx][ty + i];
            bf16 h = __float2bfloat16(v);
            hi[(ll)c * ldd + r] = h;
            lo[(ll)c * ldd + r] = __float2bfloat16(v - __bfloat162float(h));
        }
    }
}

// ---------------- fp32 SGEMM (backbone + routers + hops 1-3, R8-proven) + causal ----------------
template<bool TB, bool ACC>
__global__ void __launch_bounds__(256)
sgemm_k(const float* __restrict__ A, const float* __restrict__ B,
        float* __restrict__ C, int M, int N, int K,
        int lda, int ldb, int ldc, int inner,
        ll sAo, ll sBo, ll sCo, ll sAi, ll sBi, ll sCi, float alpha, int cmode)
{
    __shared__ float As[2][16][128];
    __shared__ float Bs[2][16][128];
    int m0 = blockIdx.y * 128, n0 = blockIdx.x * 128;
    if (cmode == 1 && n0 >= m0 + 128) return;      // score tile fully above diagonal
    if (cmode == 2) { int ke = m0 + 128; if (ke < K) K = ke; }  // PV: drop exact zeros
    int z = blockIdx.z, zo = z / inner, zi = z % inner;
    A += zo * sAo + zi * sAi;
    B += zo * sBo + zi * sBi;
    C += zo * sCo + zi * sCi;
    int tid = threadIdx.x;
    int tx = tid & 15, ty = tid >> 4;
    const int arow = tid & 127;
    const int ac4  = tid >> 7;
    float4 pa[2], pb[2];
    auto fetchA = [&](int k0) {
        const float* base = A + (ll)(m0 + arow) * lda + k0;
        pa[0] = *reinterpret_cast<const float4*>(base + ac4 * 4);
        pa[1] = *reinterpret_cast<const float4*>(base + (ac4 + 2) * 4);
    };
    auto storeA = [&](int buf) {
        #pragma unroll
        for (int i = 0; i < 2; i++) {
            int c = (ac4 + i * 2) * 4;
            As[buf][c + 0][arow] = (i ? pa[1].x : pa[0].x);
            As[buf][c + 1][arow] = (i ? pa[1].y : pa[0].y);
            As[buf][c + 2][arow] = (i ? pa[1].z : pa[0].z);
            As[buf][c + 3][arow] = (i ? pa[1].w : pa[0].w);
        }
    };
    auto fetchB = [&](int k0) {
        if (!TB) {
            bool ok = (n0 + (tid & 31) * 4) < N;
            #pragma unroll
            for (int i = 0; i < 2; i++) {
                pb[i] = ok ? *reinterpret_cast<const float4*>(
                                 B + (ll)(k0 + (tid >> 5) + i * 8) * ldb + n0 + (tid & 31) * 4)
                           : make_float4(0.f, 0.f, 0.f, 0.f);
            }
        } else {
            int gn = n0 + arow;
            bool ok = gn < N;
            const float* base = B + (ll)gn * ldb + k0;
            pb[0] = ok ? *reinterpret_cast<const float4*>(base + ac4 * 4)
                       : make_float4(0.f, 0.f, 0.f, 0.f);
            pb[1] = ok ? *reinterpret_cast<const float4*>(base + (ac4 + 2) * 4)
                       : make_float4(0.f, 0.f, 0.f, 0.f);
        }
    };
    auto storeB = [&](int buf) {
        if (!TB) {
            #pragma unroll
            for (int i = 0; i < 2; i++)
                *reinterpret_cast<float4*>(&Bs[buf][(tid >> 5) + i * 8][(tid & 31) * 4]) = pb[i];
        } else {
            #pragma unroll
            for (int i = 0; i < 2; i++) {
                int c = (ac4 + i * 2) * 4;
                Bs[buf][c + 0][arow] = (i ? pb[1].x : pb[0].x);
                Bs[buf][c + 1][arow] = (i ? pb[1].y : pb[0].y);
                Bs[buf][c + 2][arow] = (i ? pb[1].z : pb[0].z);
                Bs[buf][c + 3][arow] = (i ? pb[1].w : pb[0].w);
            }
        }
    };
    float acc[8][8];
    #pragma unroll
    for (int i = 0; i < 8; i++)
        #pragma unroll
        for (int j = 0; j < 8; j++) acc[i][j] = 0.f;
    int nk = K >> 4;
    fetchA(0); fetchB(0);
    storeA(0); storeB(0);
    __syncthreads();
    for (int kt = 0; kt < nk; kt++) {
        int cur = kt & 1;
        if (kt + 1 < nk) { fetchA((kt + 1) << 4); fetchB((kt + 1) << 4); }
        #pragma unroll
        for (int k = 0; k < 16; k++) {
            float4 a0 = *reinterpret_cast<const float4*>(&As[cur][k][ty * 8]);
            float4 a1 = *reinterpret_cast<const float4*>(&As[cur][k][ty * 8 + 4]);
            float4 b0 = *reinterpret_cast<const float4*>(&Bs[cur][k][tx * 8]);
            float4 b1 = *reinterpret_cast<const float4*>(&Bs[cur][k][tx * 8 + 4]);
            float av[8] = {a0.x, a0.y, a0.z, a0.w, a1.x, a1.y, a1.z, a1.w};
            float bv[8] = {b0.x, b0.y, b0.z, b0.w, b1.x, b1.y, b1.z, b1.w};
            #pragma unroll
            for (int i = 0; i < 8; i++)
                #pragma unroll
                for (int j = 0; j < 8; j++)
                    acc[i][j] += av[i] * bv[j];
        }
        if (kt + 1 < nk) {
            storeA(cur ^ 1); storeB(cur ^ 1);
            __syncthreads();
        }
    }
    #pragma unroll
    for (int i = 0; i < 8; i++) {
        int gm = m0 + ty * 8 + i;
        #pragma unroll
        for (int j = 0; j < 8; j++) {
            int gn = n0 + tx * 8 + j;
            if (gn >= N) continue;
            ll off = (ll)gm * ldc + gn;
            float v = alpha * acc[i][j];
            if (ACC) C[off] += v; else C[off] = v;
        }
    }
}

// ---------------- small kernels ----------------
__global__ void rope_tab_k(float* __restrict__ cs, float* __restrict__ sn)
{
    int t = blockIdx.x, i = threadIdx.x;
    int j = i & 31;
    float ex = (float)(2 * j) / 64.0f;
    float inv = (float)(1.0 / pow(10000.0, (double)ex));
    float ang = (float)t * inv;
    cs[t * HD_ + i] = cosf(ang);
    sn[t * HD_ + i] = sinf(ang);
}

__global__ void prefix_k(const float* __restrict__ cs, const float* __restrict__ sn,
                         double* __restrict__ pc, double* __restrict__ ps)
{
    int d = threadIdx.x;
    double a = 0.0, b = 0.0;
    pc[d] = 0.0; ps[d] = 0.0;
    for (int t = 0; t < T_; t++) {
        a += (double)cs[t * HD_ + d];
        b += (double)sn[t * HD_ + d];
        pc[(t + 1) * HD_ + d] = a;
        ps[(t + 1) * HD_ + d] = b;
    }
}

__global__ void embed_k(const int* __restrict__ ids, const float* __restrict__ em,
                        float* __restrict__ h)
{
    int t = blockIdx.x;
    ll r = ids[t];
    const float* src = em + r * D_;
    float* dst = h + (size_t)t * D_;
    for (int d = threadIdx.x; d < D_; d += 256) dst[d] = src[d];
}

__global__ void rmsnorm_b_k(const float* __restrict__ x, const float* __restrict__ ln,
                            float* __restrict__ y, int rowsPerE,
                            ll sxE, int slnE, ll syE)
{
    int row = blockIdx.x;
    int e = row / rowsPerE, r = row % rowsPerE;
    const float* xr = x + e * sxE + (size_t)r * D_;
    const float* lr = ln + e * slnE;
    float* yr = y + e * syE + (size_t)r * D_;
    __shared__ float red[256];
    float s = 0.f;
    for (int d = threadIdx.x; d < D_; d += 256) { float v = xr[d]; s += v * v; }
    red[threadIdx.x] = s; __syncthreads();
    for (int st = 128; st > 0; st >>= 1) {
        if (threadIdx.x < st) red[threadIdx.x] += red[threadIdx.x + st];
        __syncthreads();
    }
    float rr = rsqrtf(red[0] / (float)D_ + 1e-6f);
    for (int d = threadIdx.x; d < D_; d += 256) yr[d] = xr[d] * rr * lr[d];
}

__global__ void rope_b_k(float* __restrict__ q, float* __restrict__ k,
                         const float* __restrict__ cs, const float* __restrict__ sn,
                         int rowsPerE, int exStride)
{
    int row = blockIdx.x;
    int csRow = (row / rowsPerE) * exStride + (row % rowsPerE);
    int tid = threadIdx.x;
    int h = tid >> 5, i = tid & 31;
    float c1 = cs[csRow * HD_ + i],      s1 = sn[csRow * HD_ + i];
    float c2 = cs[csRow * HD_ + i + 32], s2 = sn[csRow * HD_ + i + 32];
    ll base = (ll)row * D_ + h * HD_ + i;
    float q0 = q[base], q1 = q[base + 32];
    q[base]      = q0 * c1 - q1 * s1;
    q[base + 32] = q1 * c2 + q0 * s2;
    float k0 = k[base], k1 = k[base + 32];
    k[base]      = k0 * c1 - k1 * s1;
    k[base + 32] = k1 * c2 + k0 * s2;
}

__global__ void softmax_causal_k(float* __restrict__ sc, int S)
{
    int i = blockIdx.x, b = blockIdx.y;
    float* row = sc + ((size_t)b * S + i) * (size_t)S;
    int valid = i + 1;
    __shared__ float red[256];
    int tid = threadIdx.x;
    float m = -1e30f;
    for (int j = tid; j < valid; j += 256) m = fmaxf(m, row[j]);
    red[tid] = m; __syncthreads();
    for (int st = 128; st > 0; st >>= 1) {
        if (tid < st) red[tid] = fmaxf(red[tid], red[tid + st]);
        __syncthreads();
    }
    m = red[0]; __syncthreads();
    float sum = 0.f;
    for (int j = tid; j < valid; j += 256) { float e = expf(row[j] - m); row[j] = e; sum += e; }
    red[tid] = sum; __syncthreads();
    for (int st = 128; st > 0; st >>= 1) {
        if (tid < st) red[tid] += red[tid + st];
        __syncthreads();
    }
    float inv = 1.0f / red[0];
    for (int j = tid; j < valid; j += 256) row[j] *= inv;
    for (int j = valid + tid; j < S; j += 256) row[j] = 0.f;
}

__global__ void gelu_k(float* __restrict__ x, ll n)
{
    for (ll i = blockIdx.x * (ll)blockDim.x + threadIdx.x; i < n;
         i += (ll)gridDim.x * blockDim.x) {
        float v = x[i];
        float t = tanhf(0.7978845608028654f * (v + 0.044715f * v * v * v));
        x[i] = 0.5f * v * (1.f + t);
    }
}

__global__ void top2_k(const float* __restrict__ lg, int* __restrict__ sel,
                       float* __restrict__ rho)
{
    int t = blockIdx.x * blockDim.x + threadIdx.x;
    if (t >= T_) return;
    const float* l = lg + (size_t)t * 9;
    int e0 = 0; float b0 = l[0];
    for (int e = 1; e < 9; e++) if (l[e] > b0) { b0 = l[e]; e0 = e; }
    int e1 = -1; float b1 = -1e30f;
    for (int e = 0; e < 9; e++) { if (e == e0) continue; if (l[e] > b1) { b1 = l[e]; e1 = e; } }
    sel[2 * t] = e0; sel[2 * t + 1] = e1;
    rho[t] = 0.5f * (float)((e0 < 8 ? 1 : 0) + (e1 < 8 ? 1 : 0));
}

// scan with built-in tail clearing (absorbs clear_k)
__global__ void scan_k(const int* __restrict__ sel, int* __restrict__ stok,
                       int* __restrict__ tslot, int* __restrict__ ecnt,
                       int* __restrict__ eov)
{
    int e = threadIdx.x;
    if (e >= 9) return;
    int cnt = 0, ov = T_;
    for (int t = 0; t < T_; t++) {
        #pragma unroll
        for (int j = 0; j < 2; j++) {
            if (sel[2 * t + j] == e) {
                int r = cnt++;
                if (r < CAP_) { stok[e * CAP_ + r] = t; tslot[2 * t + j] = r; }
                else          { tslot[2 * t + j] = -1; if (r == CAP_) ov = t; }
            }
        }
    }
    for (int r = (cnt < CAP_ ? cnt : CAP_); r < CAP_; r++) stok[e * CAP_ + r] = -1;
    ecnt[e] = cnt;
    eov[e] = ov;
}

__global__ void gather_k(const float* __restrict__ h, const int* __restrict__ stok,
                         float* __restrict__ xin)
{
    int row = blockIdx.x;
    int tok = stok[row];
    float* xo = xin + (size_t)row * D_;
    if (tok >= 0) {
        const float* hr = h + (size_t)tok * D_;
        for (int d = threadIdx.x; d < D_; d += 256) xo[d] = 0.5f * hr[d];
    } else {
        for (int d = threadIdx.x; d < D_; d += 256) xo[d] = 0.f;
    }
}

__global__ void fill_cossin_k(const int* __restrict__ stok, const int* __restrict__ ecnt,
                              const int* __restrict__ eov,
                              const double* __restrict__ pc, const double* __restrict__ ps,
                              float* __restrict__ csr, float* __restrict__ snr)
{
    int row = blockIdx.x;
    int e = row / CAP_, c = row % CAP_;
    int d = threadIdx.x;
    int m = ecnt[e];
    int mc = m < CAP_ ? m : CAP_;
    bool active = (c < mc) || (m == 0 && c == 0);
    if (!active) {
        csr[row * HD_ + d] = 0.f;
        snr[row * HD_ + d] = 0.f;
        return;
    }
    int start = (c == 0) ? 0 : stok[e * CAP_ + c];
    int end;
    if (m == 0)            end = T_;
    else if (c + 1 < m)    end = (c + 1 < CAP_) ? stok[e * CAP_ + c + 1] : eov[e];
    else                   end = T_;
    csr[row * HD_ + d] = (float)(pc[end * HD_ + d] - pc[start * HD_ + d]);
    snr[row * HD_ + d] = (float)(ps[end * HD_ + d] - ps[start * HD_ + d]);
}

// fused: h = (1 - rho[t]) * h + sum(0.5 * eout[picks])
__global__ void scale_combine_k(float* __restrict__ h, const float* __restrict__ rho,
                                const float* __restrict__ eout,
                                const int* __restrict__ sel, const int* __restrict__ tslot)
{
    int t = blockIdx.x;
    float f = 1.0f - rho[t];
    float* hr = h + (size_t)t * D_;
    int e0 = sel[2 * t], s0 = tslot[2 * t];
    int e1 = sel[2 * t + 1], s1 = tslot[2 * t + 1];
    const float* src0 = (e0 < 8 && s0 >= 0) ? eout + ((size_t)e0 * CAP_ + s0) * D_ : nullptr;
    const float* src1 = (e1 < 8 && s1 >= 0) ? eout + ((size_t)e1 * CAP_ + s1) * D_ : nullptr;
    for (int d = threadIdx.x; d < D_; d += 256) {
        float v = hr[d] * f;
        if (src0) v += 0.5f * src0[d];
        if (src1) v += 0.5f * src1[d];
        hr[d] = v;
    }
}

// ---------------- host helpers ----------------
static bf16 *BH = nullptr, *BL = nullptr;

static void gemm(bool tb, bool acc, const float* A, const float* B, float* C,
                 int M, int N, int K, int lda, int ldb, int ldc,
                 int nz, int inner,
                 ll sAo, ll sBo, ll sCo, ll sAi, ll sBi, ll sCi, float alpha, int cm)
{
    dim3 g((N + 127) / 128, M / 128, nz), b(256);
    if (!tb && !acc)      sgemm_k<false,false><<<g,b>>>(A,B,C,M,N,K,lda,ldb,ldc,inner,sAo,sBo,sCo,sAi,sBi,sCi,alpha,cm);
    else if (!tb && acc)  sgemm_k<false,true ><<<g,b>>>(A,B,C,M,N,K,lda,ldb,ldc,inner,sAo,sBo,sCo,sAi,sBi,sCi,alpha,cm);
    else if (tb && !acc)  sgemm_k<true ,false><<<g,b>>>(A,B,C,M,N,K,lda,ldb,ldc,inner,sAo,sBo,sCo,sAi,sBi,sCi,alpha,cm);
    else                  sgemm_k<true ,true ><<<g,b>>>(A,B,C,M,N,K,lda,ldb,ldc,inner,sAo,sBo,sCo,sAi,sBi,sCi,alpha,cm);
}

static void tgemmb(ll aOff, ll bOff, float* C,
                   int M, int N, int K, int lda, int ldb, int ldc,
                   int nz, int inner,
                   ll sAo, ll sBo, ll sCo, ll sAi, ll sBi, ll sCi, float alpha, int cm)
{
    dim3 g((N + 127) / 128, M / 128, nz), b(256);
    tgemm_b_k<<<g, b>>>(BH + aOff, BL + aOff, BH + bOff, BL + bOff, C,
                        M, N, K, lda, ldb, ldc, inner,
                        sAo, sBo, sCo, sAi, sBi, sCi, alpha, cm);
}

static void conv(const float* x, ll bOff, ll n)
{
    int blocks = (int)((n + 255) / 256);
    if (blocks > 4096) blocks = 4096;
    conv_k<<<blocks, 256>>>(x, BH + bOff, BL + bOff, n);
}

static void convT(const float* src, ll bOff, int R, int C, int lds, int ldd,
                  int nz, int inner, ll sSo, ll sDo, ll sSi, ll sDi)
{
    dim3 g((C + 31) / 32, (R + 31) / 32, nz), b(32, 8);
    convT_k<<<g, b>>>(src, BH + bOff, BL + bOff, R, C, lds, ldd, inner,
                      sSo, sDo, sSi, sDi);
}

// ---------------- entry point ----------------
extern "C" void kernel_launch(void* const* d_in, const int* in_sizes, int n_in,
                              void* d_out, int out_size)
{
    (void)in_sizes; (void)n_in; (void)out_size;
    const int*   ids     = (const int*)  d_in[0];
    const float* embed   = (const float*)d_in[1];
    const float* routerW = (const float*)d_in[2];
    const float* b_aln   = (const float*)d_in[3];
    const float* b_wq    = (const float*)d_in[4];
    const float* b_wk    = (const float*)d_in[5];
    const float* b_wv    = (const float*)d_in[6];
    const float* b_wo    = (const float*)d_in[7];
    const float* b_fln   = (const float*)d_in[8];
    const float* b_w1    = (const float*)d_in[9];
    const float* b_w2    = (const float*)d_in[10];
    const float* a_ln    = (const float*)d_in[11];
    const float* a_wq    = (const float*)d_in[12];
    const float* a_wk    = (const float*)d_in[13];
    const float* a_wv    = (const float*)d_in[14];
    const float* a_wo    = (const float*)d_in[15];
    const float* f_ln    = (const float*)d_in[16];
    const float* f_w1    = (const float*)d_in[17];
    const float* f_w2    = (const float*)d_in[18];
    const float* ln_out  = (const float*)d_in[19];
    float* out = (float*)d_out;

    float* W = nullptr; int* WI = nullptr; double* WD = nullptr;
    cudaGetSymbolAddress((void**)&W,  g_ws);
    cudaGetSymbolAddress((void**)&WI, g_wsi);
    cudaGetSymbolAddress((void**)&WD, g_wsd);
    cudaGetSymbolAddress((void**)&BH, g_bh);
    cudaGetSymbolAddress((void**)&BL, g_bl);

    float *Hh  = W + OFF_H,   *XN  = W + OFF_XN,  *Q   = W + OFF_Q,
          *Kb  = W + OFF_K,   *Vb  = W + OFF_V,   *AO  = W + OFF_AO,
          *FF  = W + OFF_FFN, *SC  = W + OFF_SC,  *XIN = W + OFF_XIN,
          *EOUT= W + OFF_EOUT,*CS  = W + OFF_COS, *SN  = W + OFF_SIN,
          *CSR = W + OFF_COSR,*SNR = W + OFF_SINR,*LG  = W + OFF_LG,
          *RHO = W + OFF_RHO;
    double *PC = WD + OFF_PC, *PS = WD + OFF_PS;
    int *SEL = WI + IOFF_SEL, *STOK = WI + IOFF_STOK, *TSLOT = WI + IOFF_TSLOT,
        *ECNT = WI + IOFF_ECNT, *EOV = WI + IOFF_EOV;

    const ll CD  = (ll)CAP_ * D_;
    const ll DD  = (ll)D_ * D_;
    const ll CC  = (ll)CAP_ * CAP_;
    const ll CF  = (ll)CAP_ * DFF_;
    const ll DF  = (ll)D_ * DFF_;

    // one-time bf16 conversions: embed + hop-4 expert weights (transposed n x k)
    conv(embed, BO_EMB, VDc);
    convT(a_wq, BO_AWQ, D_, D_, D_, D_, 4, 1, DD, DD, 0, 0);
    convT(a_wk, BO_AWK, D_, D_, D_, D_, 4, 1, DD, DD, 0, 0);
    convT(a_wv, BO_AWV, D_, D_, D_, D_, 4, 1, DD, DD, 0, 0);
    convT(a_wo, BO_AWO, D_, D_, D_, D_, 4, 1, DD, DD, 0, 0);
    convT(f_w1, BO_FW1, D_, DFF_, DFF_, D_, 4, 1, DF, DF, 0, 0);
    convT(f_w2, BO_FW2, DFF_, D_, D_, DFF_, 4, 1, DF, DF, 0, 0);

    // rope tables + prefix sums + embedding
    rope_tab_k<<<T_, HD_>>>(CS, SN);
    prefix_k<<<1, HD_>>>(CS, SN, PC, PS);
    embed_k<<<T_, 256>>>(ids, embed, Hh);

    // ---------------- backbone attention (fp32) ----------------
    rmsnorm_b_k<<<T_, 256>>>(Hh, b_aln, XN, T_, 0, 0, 0);
    gemm(false,false, XN, b_wq, Q,  T_, D_, D_, D_, D_, D_, 1,1, 0,0,0, 0,0,0, 1.f, 0);
    gemm(false,false, XN, b_wk, Kb, T_, D_, D_, D_, D_, D_, 1,1, 0,0,0, 0,0,0, 1.f, 0);
    gemm(false,false, XN, b_wv, Vb, T_, D_, D_, D_, D_, D_, 1,1, 0,0,0, 0,0,0, 1.f, 0);
    rope_b_k<<<T_, H_ * 32>>>(Q, Kb, CS, SN, T_, 0);
    gemm(true, false, Q, Kb, SC, T_, T_, HD_, D_, D_, T_,
         H_, H_, 0,0,0, HD_, HD_, (ll)T_ * T_, 0.125f, 1);          // causal skip
    softmax_causal_k<<<dim3(T_, H_), 256>>>(SC, T_);
    gemm(false,false, SC, Vb, AO, T_, HD_, T_, T_, D_, D_,
         H_, H_, 0,0,0, (ll)T_ * T_, HD_, HD_, 1.f, 2);             // K-clamp
    gemm(false,true, AO, b_wo, Hh, T_, D_, D_, D_, D_, D_, 1,1, 0,0,0, 0,0,0, 1.f, 0);

    // ---------------- backbone FFN (fp32) ----------------
    rmsnorm_b_k<<<T_, 256>>>(Hh, b_fln, XN, T_, 0, 0, 0);
    gemm(false,false, XN, b_w1, FF, T_, DFF_, D_, D_, DFF_, DFF_, 1,1, 0,0,0, 0,0,0, 1.f, 0);
    gelu_k<<<2048, 256>>>(FF, (ll)T_ * DFF_);
    gemm(false,true, FF, b_w2, Hh, T_, D_, DFF_, DFF_, D_, D_, 1,1, 0,0,0, 0,0,0, 1.f, 0);

    for (int r = 0; r < NHOPS_; r++) {
        gemm(true, false, Hh, routerW + (size_t)r * 9 * D_, LG,
             T_, 9, D_, D_, D_, 9, 1,1, 0,0,0, 0,0,0, 1.f, 0);
        top2_k<<<(T_ + 255) / 256, 256>>>(LG, SEL, RHO);
        scan_k<<<1, 32>>>(SEL, STOK, TSLOT, ECNT, EOV);
        gather_k<<<8 * CAP_, 256>>>(Hh, STOK, XIN);
        fill_cossin_k<<<8 * CAP_, HD_>>>(STOK, ECNT, EOV, PC, PS, CSR, SNR);

        if (r < NHOPS_ - 1) {
            // ===== hops 1-3: fp32 expert phase (routing-sensitive; exact) =====
            rmsnorm_b_k<<<4 * CAP_, 256>>>(XIN, a_ln, XN, CAP_, 2 * CD, D_, CD);
            gemm(false,false, XN, a_wq, Q,  CAP_, D_, D_, D_, D_, D_,
                 4,1, CD, DD, CD, 0,0,0, 1.f, 0);
            gemm(false,false, XN, a_wk, Kb, CAP_, D_, D_, D_, D_, D_,
                 4,1, CD, DD, CD, 0,0,0, 1.f, 0);
            gemm(false,false, XN, a_wv, Vb, CAP_, D_, D_, D_, D_, D_,
                 4,1, CD, DD, CD, 0,0,0, 1.f, 0);
            rope_b_k<<<4 * CAP_, H_ * 32>>>(Q, Kb, CSR, SNR, CAP_, 2 * CAP_);
            gemm(true, false, Q, Kb, SC, CAP_, CAP_, HD_, D_, D_, CAP_,
                 4 * H_, H_, CD, CD, 16 * CC, HD_, HD_, CC, 0.125f, 1);
            softmax_causal_k<<<dim3(CAP_, 4 * H_), 256>>>(SC, CAP_);
            gemm(false,false, SC, Vb, AO, CAP_, HD_, CAP_, CAP_, D_, D_,
                 4 * H_, H_, 16 * CC, CD, CD, CC, HD_, HD_, 1.f, 2);
            gemm(false,false, AO, a_wo, EOUT, CAP_, D_, D_, D_, D_, D_,
                 4,1, CD, DD, CD, 0,0,0, 1.f, 0);

            rmsnorm_b_k<<<4 * CAP_, 256>>>(XIN + CD, f_ln, XN, CAP_, 2 * CD, D_, CD);
            gemm(false,false, XN, f_w1, FF, CAP_, DFF_, D_, D_, DFF_, DFF_,
                 4,1, CD, DF, CF, 0,0,0, 1.f, 0);
            gelu_k<<<2048, 256>>>(FF, (ll)4 * CAP_ * DFF_);
            gemm(false,false, FF, f_w2, EOUT + 4 * CD, CAP_, D_, DFF_, DFF_, D_, D_,
                 4,1, CF, DF, CD, 0,0,0, 1.f, 0);
        } else {
            // ===== hop 4: bf16 tensor expert phase (no downstream router; R14-proven) =====
            rmsnorm_b_k<<<4 * CAP_, 256>>>(XIN, a_ln, XN, CAP_, 2 * CD, D_, CD);
            conv(XN, BO_XN, TDc);
            tgemmb(BO_XN, BO_AWQ, Q,  CAP_, D_, D_, D_, D_, D_,
                   4,1, CD, DD, CD, 0,0,0, 1.f, 0);
            tgemmb(BO_XN, BO_AWK, Kb, CAP_, D_, D_, D_, D_, D_,
                   4,1, CD, DD, CD, 0,0,0, 1.f, 0);
            tgemmb(BO_XN, BO_AWV, Vb, CAP_, D_, D_, D_, D_, D_,
                   4,1, CD, DD, CD, 0,0,0, 1.f, 0);
            rope_b_k<<<4 * CAP_, H_ * 32>>>(Q, Kb, CSR, SNR, CAP_, 2 * CAP_);
            conv(Q, BO_Q, 2 * TDc);
            convT(Vb, BO_VT, CAP_, HD_, D_, CAP_, 4 * H_, H_,
                  CD, CD, HD_, (ll)HD_ * CAP_);
            tgemmb(BO_Q, BO_K, SC, CAP_, CAP_, HD_, D_, D_, CAP_,
                   4 * H_, H_, CD, CD, 16 * CC, HD_, HD_, CC, 0.125f, 1);
            softmax_causal_k<<<dim3(CAP_, 4 * H_), 256>>>(SC, CAP_);
            conv(SC, BO_SC, (ll)4 * H_ * CC);
            tgemmb(BO_SC, BO_VT, AO, CAP_, HD_, CAP_, CAP_, CAP_, D_,
                   4 * H_, H_, 16 * CC, CD, CD, CC, (ll)HD_ * CAP_, HD_, 1.f, 2);
            conv(AO, BO_AO, TDc);
            tgemmb(BO_AO, BO_AWO, EOUT, CAP_, D_, D_, D_, D_, D_,
                   4,1, CD, DD, CD, 0,0,0, 1.f, 0);

            rmsnorm_b_k<<<4 * CAP_, 256>>>(XIN + CD, f_ln, XN, CAP_, 2 * CD, D_, CD);
            conv(XN, BO_XN, TDc);
            tgemmb(BO_XN, BO_FW1, FF, CAP_, DFF_, D_, D_, D_, DFF_,
                   4,1, CD, DF, CF, 0,0,0, 1.f, 0);
            gelu_k<<<2048, 256>>>(FF, (ll)4 * CAP_ * DFF_);
            conv(FF, BO_FF, (ll)4 * CF);
            tgemmb(BO_FF, BO_FW2, EOUT + 4 * CD, CAP_, D_, DFF_, DFF_, DFF_, D_,
                   4,1, CF, DF, CD, 0,0,0, 1.f, 0);
        }

        scale_combine_k<<<T_, 256>>>(Hh, RHO, EOUT, SEL, TSLOT);
    }

    // final: rms(h)*ln_out @ embed^T — bf16 2-way 4-term tensor GEMM (proven)
    rmsnorm_b_k<<<T_, 256>>>(Hh, ln_out, XN, T_, 0, 0, 0);
    conv_k<<<2048, 256>>>(XN, BH + BO_XNO, BL + BO_XNO, TDc);
    {
        dim3 g(V_ / 128, T_ / 128, 1), b(256);
        tgemm_k<<<g, b>>>(BH + BO_XNO, BL + BO_XNO, BH + BO_EMB, BL + BO_EMB,
                          out, T_, V_, D_, D_, D_, V_, 1.f);
    }
}